// round 4
// baseline (speedup 1.0000x reference)
#include <cuda_runtime.h>

#define NN 50000
#define NE 800000

// ---------------- scratch (static device globals; no allocs) ----------------
__device__ float g_ew[NE];
__device__ float g_deg[NN];
__device__ float g_dinv[NN];
__device__ int   g_cnt[NN];
__device__ int   g_rowptr[NN + 1];
__device__ int   g_cur[NN];
__device__ int   g_csr_src[NE];
__device__ float g_csr_w[NE];
// 5 node-feature buffers of [NN x 64]: 0,1,2 = hop buffers, 3,4 = layer ping-pong
struct alignas(16) NFBuf { float v[5][NN * 64]; };
__device__ NFBuf g_nf;

// ---------------- init ----------------
__global__ void k_zero() {
    int i = blockIdx.x * blockDim.x + threadIdx.x;
    if (i < NN) { g_deg[i] = 0.f; g_cnt[i] = 0; }
}

// ---------------- edge MLP -> ew, plus deg & count histograms ----------------
// NOTE: edge_index is int32 (JAX x64 disabled downcasts jnp.int64 -> int32).
__global__ void k_edge(const float* __restrict__ ea, const int* __restrict__ ei,
                       const float* __restrict__ W1, const float* __restrict__ b1,
                       const float* __restrict__ W2, const float* __restrict__ b2) {
    __shared__ float sW1[512];
    __shared__ float sb1[64];
    __shared__ float sW2[64];
    __shared__ float sb2;
    for (int i = threadIdx.x; i < 512; i += blockDim.x) sW1[i] = W1[i];
    if (threadIdx.x < 64) { sb1[threadIdx.x] = b1[threadIdx.x]; sW2[threadIdx.x] = W2[threadIdx.x]; }
    if (threadIdx.x == 0) sb2 = b2[0];
    __syncthreads();

    int e = blockIdx.x * blockDim.x + threadIdx.x;
    if (e >= NE) return;

    float4 v0 = reinterpret_cast<const float4*>(ea)[e * 2];
    float4 v1 = reinterpret_cast<const float4*>(ea)[e * 2 + 1];
    float a0 = v0.x, a1 = v0.y, a2 = v0.z, a3 = v0.w;
    float a4 = v1.x, a5 = v1.y, a6 = v1.z, a7 = v1.w;

    float ew = sb2;
#pragma unroll 8
    for (int j = 0; j < 64; j++) {
        float h = sb1[j];
        h = fmaf(a0, sW1[j],        h);
        h = fmaf(a1, sW1[64 + j],   h);
        h = fmaf(a2, sW1[128 + j],  h);
        h = fmaf(a3, sW1[192 + j],  h);
        h = fmaf(a4, sW1[256 + j],  h);
        h = fmaf(a5, sW1[320 + j],  h);
        h = fmaf(a6, sW1[384 + j],  h);
        h = fmaf(a7, sW1[448 + j],  h);
        ew = fmaf(fmaxf(h, 0.f), sW2[j], ew);
    }
    g_ew[e] = ew;
    int dst = ei[NE + e];
    atomicAdd(&g_deg[dst], ew);
    atomicAdd(&g_cnt[dst], 1);
}

__global__ void k_dinv() {
    int i = blockIdx.x * blockDim.x + threadIdx.x;
    if (i < NN) {
        float d = g_deg[i];
        g_dinv[i] = (d > 0.f) ? rsqrtf(d) : 0.f;
    }
}

// ---------------- single-block exclusive scan over counts -> rowptr ----------------
__global__ void k_scan() {
    __shared__ int part[1024];
    const int tid = threadIdx.x;
    const int CH = (NN + 1023) / 1024;  // 49
    int base = tid * CH;
    int s = 0;
    for (int i = 0; i < CH; i++) {
        int idx = base + i;
        if (idx < NN) s += g_cnt[idx];
    }
    part[tid] = s;
    __syncthreads();
    // Hillis-Steele inclusive scan
    for (int off = 1; off < 1024; off <<= 1) {
        int v = (tid >= off) ? part[tid - off] : 0;
        __syncthreads();
        part[tid] += v;
        __syncthreads();
    }
    int prefix = (tid == 0) ? 0 : part[tid - 1];
    for (int i = 0; i < CH; i++) {
        int idx = base + i;
        if (idx < NN) {
            int c = g_cnt[idx];
            g_rowptr[idx] = prefix;
            g_cur[idx]    = prefix;
            prefix += c;
        }
    }
    if (tid == 1023) g_rowptr[NN] = prefix;  // == NE
}

// ---------------- fill CSR (by dst) with fused normalized weight ----------------
__global__ void k_fill(const int* __restrict__ ei) {
    int e = blockIdx.x * blockDim.x + threadIdx.x;
    if (e >= NE) return;
    int src = ei[e];
    int dst = ei[NE + e];
    float w = g_dinv[src] * g_ew[e] * g_dinv[dst];
    int pos = atomicAdd(&g_cur[dst], 1);
    g_csr_src[pos] = src;
    g_csr_w[pos]   = w;
}

// ---------------- propagation: h_out[n] = sum_{e->n} w_e * h_in[src_e] ----------------
// F=64: one warp per node, 2 features per lane
__global__ void k_prop64(int isel, int osel) {
    int g    = blockIdx.x * blockDim.x + threadIdx.x;
    int node = g >> 5;
    int lane = g & 31;
    if (node >= NN) return;
    const float* __restrict__ hin  = g_nf.v[isel];
    float* __restrict__       hout = g_nf.v[osel];
    int beg = g_rowptr[node], end = g_rowptr[node + 1];
    float acc0 = 0.f, acc1 = 0.f;
    int p = beg;
    for (; p + 1 < end; p += 2) {
        int   s0 = g_csr_src[p],     s1 = g_csr_src[p + 1];
        float w0 = g_csr_w[p],       w1 = g_csr_w[p + 1];
        const float* r0 = hin + (size_t)s0 * 64;
        const float* r1 = hin + (size_t)s1 * 64;
        float x0 = __ldg(r0 + lane), y0 = __ldg(r0 + lane + 32);
        float x1 = __ldg(r1 + lane), y1 = __ldg(r1 + lane + 32);
        acc0 = fmaf(w0, x0, acc0); acc1 = fmaf(w0, y0, acc1);
        acc0 = fmaf(w1, x1, acc0); acc1 = fmaf(w1, y1, acc1);
    }
    if (p < end) {
        int s = g_csr_src[p];
        float w = g_csr_w[p];
        const float* r = hin + (size_t)s * 64;
        acc0 = fmaf(w, __ldg(r + lane),      acc0);
        acc1 = fmaf(w, __ldg(r + lane + 32), acc1);
    }
    hout[(size_t)node * 64 + lane]      = acc0;
    hout[(size_t)node * 64 + lane + 32] = acc1;
}

// F=16: 16 threads per node (2 nodes per warp)
__global__ void k_prop16(const float* __restrict__ ext, int isel, int osel) {
    int g    = blockIdx.x * blockDim.x + threadIdx.x;
    int node = g >> 4;
    int f    = g & 15;
    if (node >= NN) return;
    const float* __restrict__ hin  = (isel < 0) ? ext : g_nf.v[isel];
    float* __restrict__       hout = g_nf.v[osel];
    int beg = g_rowptr[node], end = g_rowptr[node + 1];
    float acc = 0.f;
    for (int p = beg; p < end; p++) {
        acc = fmaf(g_csr_w[p], __ldg(hin + (size_t)g_csr_src[p] * 16 + f), acc);
    }
    hout[(size_t)node * 16 + f] = acc;
}

// ---------------- fused TAGConv GEMM: out = [h0|h1|h2|h3] @ W + b (opt relu) --------
// BM=128 rows/block, 128 threads, each thread computes 8 rows x (FOUT/8) cols.
template <int FIN, int FOUT, int SK, bool RELU>
__global__ void k_gemm(const float* __restrict__ ext0, int i0sel,
                       const float* __restrict__ W, const float* __restrict__ bias,
                       float* __restrict__ ext_out, int osel) {
    constexpr int BM  = 128;
    constexpr int KD  = 4 * FIN;
    constexpr int NCH = KD / SK;
    constexpr int TN  = FOUT / 8;

    __shared__ float hs[BM][SK + 1];
    __shared__ float ws[SK][FOUT];

    const float* hb[4];
    hb[0] = (i0sel < 0) ? ext0 : g_nf.v[i0sel];
    hb[1] = g_nf.v[0];
    hb[2] = g_nf.v[1];
    hb[3] = g_nf.v[2];
    float* out = (osel < 0) ? ext_out : g_nf.v[osel];

    int row0 = blockIdx.x * BM;
    int tid  = threadIdx.x;
    int trow = tid >> 3;   // 0..15
    int tcol = tid & 7;    // 0..7
    int myrow = row0 + tid;

    float acc[8][TN];
#pragma unroll
    for (int m = 0; m < 8; m++)
#pragma unroll
        for (int n = 0; n < TN; n++) acc[m][n] = 0.f;

    for (int c = 0; c < NCH; c++) {
        int gi0 = c * SK;
        const float* hp = hb[gi0 / FIN];
        int off = gi0 % FIN;
        // stage h tile: thread tid stages row (row0+tid)
        if (myrow < NN) {
            const float4* s4 = reinterpret_cast<const float4*>(hp + (size_t)myrow * FIN + off);
#pragma unroll
            for (int q = 0; q < SK / 4; q++) {
                float4 v = s4[q];
                hs[tid][q * 4 + 0] = v.x;
                hs[tid][q * 4 + 1] = v.y;
                hs[tid][q * 4 + 2] = v.z;
                hs[tid][q * 4 + 3] = v.w;
            }
        } else {
#pragma unroll
            for (int q = 0; q < SK; q++) hs[tid][q] = 0.f;
        }
        // stage W tile (contiguous)
        for (int idx = tid; idx < SK * FOUT; idx += BM)
            ((float*)ws)[idx] = W[gi0 * FOUT + idx];
        __syncthreads();

#pragma unroll
        for (int i = 0; i < SK; i++) {
            float hr[8];
#pragma unroll
            for (int m = 0; m < 8; m++) hr[m] = hs[trow * 8 + m][i];
            float wv[TN];
#pragma unroll
            for (int n = 0; n < TN; n++) wv[n] = ws[i][n * 8 + tcol];
#pragma unroll
            for (int m = 0; m < 8; m++)
#pragma unroll
                for (int n = 0; n < TN; n++)
                    acc[m][n] = fmaf(hr[m], wv[n], acc[m][n]);
        }
        __syncthreads();
    }

#pragma unroll
    for (int m = 0; m < 8; m++) {
        int r = row0 + trow * 8 + m;
        if (r < NN) {
#pragma unroll
            for (int n = 0; n < TN; n++) {
                int j = n * 8 + tcol;
                float v = acc[m][n] + bias[j];
                if (RELU) v = fmaxf(v, 0.f);
                out[(size_t)r * FOUT + j] = v;
            }
        }
    }
}

// ---------------- launch ----------------
extern "C" void kernel_launch(void* const* d_in, const int* in_sizes, int n_in,
                              void* d_out, int out_size) {
    const float* x  = (const float*)d_in[0];
    const int*   ei = (const int*)d_in[1];     // int32! (JAX x64 disabled)
    const float* ea = (const float*)d_in[2];
    const float* W1 = (const float*)d_in[3];
    const float* b1 = (const float*)d_in[4];
    const float* W2 = (const float*)d_in[5];
    const float* b2 = (const float*)d_in[6];
    const float* Wf = (const float*)d_in[7];
    const float* bf = (const float*)d_in[8];
    const float* Wm = (const float*)d_in[9];
    const float* bm = (const float*)d_in[10];
    const float* Wl = (const float*)d_in[11];
    const float* bl = (const float*)d_in[12];
    float*       out = (float*)d_out;

    const int NB_N   = (NN + 255) / 256;
    const int NB_E   = (NE + 255) / 256;
    const int NB_P64 = (NN * 32 + 255) / 256;  // warp per node
    const int NB_P16 = (NN * 16 + 255) / 256;  // 16 threads per node
    const int NB_G   = (NN + 127) / 128;

    // preprocessing: edge weights, gcn norm, CSR build
    k_zero<<<NB_N, 256>>>();
    k_edge<<<NB_E, 256>>>(ea, ei, W1, b1, W2, b2);
    k_dinv<<<NB_N, 256>>>();
    k_scan<<<1, 1024>>>();
    k_fill<<<NB_E, 256>>>(ei);

    // layer 0: FIN=16 -> 64, relu
    k_prop16<<<NB_P16, 256>>>(x, -1, 0);
    k_prop16<<<NB_P16, 256>>>(nullptr, 0, 1);
    k_prop16<<<NB_P16, 256>>>(nullptr, 1, 2);
    k_gemm<16, 64, 16, true><<<NB_G, 128>>>(x, -1, Wf, bf, nullptr, 3);

    // mid layer 0: 64 -> 64, relu
    k_prop64<<<NB_P64, 256>>>(3, 0);
    k_prop64<<<NB_P64, 256>>>(0, 1);
    k_prop64<<<NB_P64, 256>>>(1, 2);
    k_gemm<64, 64, 32, true><<<NB_G, 128>>>(nullptr, 3, Wm, bm, nullptr, 4);

    // mid layer 1: 64 -> 64, relu
    k_prop64<<<NB_P64, 256>>>(4, 0);
    k_prop64<<<NB_P64, 256>>>(0, 1);
    k_prop64<<<NB_P64, 256>>>(1, 2);
    k_gemm<64, 64, 32, true><<<NB_G, 128>>>(nullptr, 4, Wm + 4 * 64 * 64, bm + 64, nullptr, 3);

    // last layer: 64 -> 8, no relu, writes d_out
    k_prop64<<<NB_P64, 256>>>(3, 0);
    k_prop64<<<NB_P64, 256>>>(0, 1);
    k_prop64<<<NB_P64, 256>>>(1, 2);
    k_gemm<64, 8, 32, false><<<NB_G, 128>>>(nullptr, 3, Wl, bl, out, -1);
}

// round 5
// speedup vs baseline: 1.2892x; 1.2892x over previous
#include <cuda_runtime.h>

#define NN 50000
#define NE 800000
#define SCAN_B 512
#define SCAN_NBLK ((NN + SCAN_B - 1) / SCAN_B)   // 98

// ---------------- scratch (static device globals; no allocs) ----------------
__device__ float g_ew[NE];
__device__ float g_deg[NN];
__device__ float g_dinv[NN];
__device__ int   g_cnt[NN];
__device__ int   g_rowptr[NN + 1];
__device__ int   g_cur[NN];
__device__ int   g_csr_src[NE];
__device__ float g_csr_w[NE];
__device__ int   g_psum[SCAN_NBLK];
__device__ int   g_poff[SCAN_NBLK];
// 5 node-feature buffers of [NN x 64]: 0,1,2 = hop buffers, 3,4 = layer ping-pong
struct alignas(16) NFBuf { float v[5][NN * 64]; };
__device__ NFBuf g_nf;

// ---------------- init ----------------
__global__ void k_zero() {
    int i = blockIdx.x * blockDim.x + threadIdx.x;
    if (i < NN) { g_deg[i] = 0.f; g_cnt[i] = 0; }
}

// ---------------- edge MLP -> ew, plus deg & count histograms ----------------
// NOTE: edge_index is int32 (JAX x64 disabled downcasts jnp.int64 -> int32).
__global__ void k_edge(const float* __restrict__ ea, const int* __restrict__ ei,
                       const float* __restrict__ W1, const float* __restrict__ b1,
                       const float* __restrict__ W2, const float* __restrict__ b2) {
    __shared__ float sW1[512];
    __shared__ float sb1[64];
    __shared__ float sW2[64];
    __shared__ float sb2;
    for (int i = threadIdx.x; i < 512; i += blockDim.x) sW1[i] = W1[i];
    if (threadIdx.x < 64) { sb1[threadIdx.x] = b1[threadIdx.x]; sW2[threadIdx.x] = W2[threadIdx.x]; }
    if (threadIdx.x == 0) sb2 = b2[0];
    __syncthreads();

    int e = blockIdx.x * blockDim.x + threadIdx.x;
    if (e >= NE) return;

    float4 v0 = reinterpret_cast<const float4*>(ea)[e * 2];
    float4 v1 = reinterpret_cast<const float4*>(ea)[e * 2 + 1];
    float a0 = v0.x, a1 = v0.y, a2 = v0.z, a3 = v0.w;
    float a4 = v1.x, a5 = v1.y, a6 = v1.z, a7 = v1.w;

    float ew = sb2;
#pragma unroll 8
    for (int j = 0; j < 64; j++) {
        float h = sb1[j];
        h = fmaf(a0, sW1[j],        h);
        h = fmaf(a1, sW1[64 + j],   h);
        h = fmaf(a2, sW1[128 + j],  h);
        h = fmaf(a3, sW1[192 + j],  h);
        h = fmaf(a4, sW1[256 + j],  h);
        h = fmaf(a5, sW1[320 + j],  h);
        h = fmaf(a6, sW1[384 + j],  h);
        h = fmaf(a7, sW1[448 + j],  h);
        ew = fmaf(fmaxf(h, 0.f), sW2[j], ew);
    }
    g_ew[e] = ew;
    int dst = ei[NE + e];
    atomicAdd(&g_deg[dst], ew);
    atomicAdd(&g_cnt[dst], 1);
}

// ---------------- multi-block scan over counts -> rowptr (3 tiny kernels) --------
// pass 1: per-block reduction of counts; also compute dinv (deg already final)
__global__ void k_scan1() {
    __shared__ int red[SCAN_B / 32];
    int b = blockIdx.x, t = threadIdx.x;
    int i = b * SCAN_B + t;
    int c = (i < NN) ? g_cnt[i] : 0;
    if (i < NN) {
        float d = g_deg[i];
        g_dinv[i] = (d > 0.f) ? rsqrtf(d) : 0.f;
    }
    int v = c;
#pragma unroll
    for (int o = 16; o; o >>= 1) v += __shfl_down_sync(0xffffffffu, v, o);
    if ((t & 31) == 0) red[t >> 5] = v;
    __syncthreads();
    if (t == 0) {
        int s = 0;
#pragma unroll
        for (int w = 0; w < SCAN_B / 32; w++) s += red[w];
        g_psum[b] = s;
    }
}
// pass 2: serial scan over 98 block sums (trivial)
__global__ void k_scan2() {
    if (threadIdx.x == 0) {
        int acc = 0;
        for (int b = 0; b < SCAN_NBLK; b++) { g_poff[b] = acc; acc += g_psum[b]; }
        g_rowptr[NN] = acc;   // == NE
    }
}
// pass 3: per-block exclusive scan + global offset -> rowptr, cur
__global__ void k_scan3() {
    __shared__ int sc[SCAN_B];
    int b = blockIdx.x, t = threadIdx.x;
    int i = b * SCAN_B + t;
    int c = (i < NN) ? g_cnt[i] : 0;
    sc[t] = c;
    __syncthreads();
#pragma unroll
    for (int off = 1; off < SCAN_B; off <<= 1) {
        int v = (t >= off) ? sc[t - off] : 0;
        __syncthreads();
        sc[t] += v;
        __syncthreads();
    }
    if (i < NN) {
        int excl = sc[t] - c + g_poff[b];
        g_rowptr[i] = excl;
        g_cur[i]    = excl;
    }
}

// ---------------- fill CSR (by dst) with fused normalized weight ----------------
__global__ void k_fill(const int* __restrict__ ei) {
    int e = blockIdx.x * blockDim.x + threadIdx.x;
    if (e >= NE) return;
    int src = ei[e];
    int dst = ei[NE + e];
    float w = g_dinv[src] * g_ew[e] * g_dinv[dst];
    int pos = atomicAdd(&g_cur[dst], 1);
    g_csr_src[pos] = src;
    g_csr_w[pos]   = w;
}

// ---------------- propagation: h_out[n] = sum_{e->n} w_e * h_in[src_e] ----------------
// F=64: one warp per node, 2 features per lane
__global__ void k_prop64(int isel, int osel) {
    int g    = blockIdx.x * blockDim.x + threadIdx.x;
    int node = g >> 5;
    int lane = g & 31;
    if (node >= NN) return;
    const float* __restrict__ hin  = g_nf.v[isel];
    float* __restrict__       hout = g_nf.v[osel];
    int beg = g_rowptr[node], end = g_rowptr[node + 1];
    float acc0 = 0.f, acc1 = 0.f;
    int p = beg;
    for (; p + 1 < end; p += 2) {
        int   s0 = g_csr_src[p],     s1 = g_csr_src[p + 1];
        float w0 = g_csr_w[p],       w1 = g_csr_w[p + 1];
        const float* r0 = hin + (size_t)s0 * 64;
        const float* r1 = hin + (size_t)s1 * 64;
        float x0 = __ldg(r0 + lane), y0 = __ldg(r0 + lane + 32);
        float x1 = __ldg(r1 + lane), y1 = __ldg(r1 + lane + 32);
        acc0 = fmaf(w0, x0, acc0); acc1 = fmaf(w0, y0, acc1);
        acc0 = fmaf(w1, x1, acc0); acc1 = fmaf(w1, y1, acc1);
    }
    if (p < end) {
        int s = g_csr_src[p];
        float w = g_csr_w[p];
        const float* r = hin + (size_t)s * 64;
        acc0 = fmaf(w, __ldg(r + lane),      acc0);
        acc1 = fmaf(w, __ldg(r + lane + 32), acc1);
    }
    hout[(size_t)node * 64 + lane]      = acc0;
    hout[(size_t)node * 64 + lane + 32] = acc1;
}

// F=16: 16 threads per node (2 nodes per warp)
__global__ void k_prop16(const float* __restrict__ ext, int isel, int osel) {
    int g    = blockIdx.x * blockDim.x + threadIdx.x;
    int node = g >> 4;
    int f    = g & 15;
    if (node >= NN) return;
    const float* __restrict__ hin  = (isel < 0) ? ext : g_nf.v[isel];
    float* __restrict__       hout = g_nf.v[osel];
    int beg = g_rowptr[node], end = g_rowptr[node + 1];
    float acc = 0.f;
    for (int p = beg; p < end; p++) {
        acc = fmaf(g_csr_w[p], __ldg(hin + (size_t)g_csr_src[p] * 16 + f), acc);
    }
    hout[(size_t)node * 16 + f] = acc;
}

// F=8 Horner hop: out[n] = (A tin)[n] + yadd[n] (+ bias). out stride fixed = 8.
__global__ void k_prop8(int tin_sel, int tin_off, int tin_stride,
                        int y_sel, int y_off, int y_stride,
                        const float* __restrict__ bias,
                        float* __restrict__ ext_out, int out_sel) {
    int g    = blockIdx.x * blockDim.x + threadIdx.x;
    int node = g >> 3;
    int f    = g & 7;
    if (node >= NN) return;
    const float* __restrict__ tin = g_nf.v[tin_sel] + tin_off;
    const float* __restrict__ ya  = g_nf.v[y_sel]  + y_off;
    float* __restrict__ outp = ext_out ? ext_out : g_nf.v[out_sel];
    int beg = g_rowptr[node], end = g_rowptr[node + 1];
    float acc0 = 0.f, acc1 = 0.f;
    int p = beg;
    for (; p + 1 < end; p += 2) {
        int   s0 = g_csr_src[p],  s1 = g_csr_src[p + 1];
        float w0 = g_csr_w[p],    w1 = g_csr_w[p + 1];
        acc0 = fmaf(w0, __ldg(tin + (size_t)s0 * tin_stride + f), acc0);
        acc1 = fmaf(w1, __ldg(tin + (size_t)s1 * tin_stride + f), acc1);
    }
    if (p < end)
        acc0 = fmaf(g_csr_w[p], __ldg(tin + (size_t)g_csr_src[p] * tin_stride + f), acc0);
    float v = acc0 + acc1 + ya[(size_t)node * y_stride + f];
    if (bias) v += bias[f];
    outp[(size_t)node * 8 + f] = v;
}

// ---------------- fused TAGConv GEMM: out = [h0|h1|h2|h3] @ W + b (opt relu) --------
template <int FIN, int FOUT, int SK, bool RELU>
__global__ void k_gemm(const float* __restrict__ ext0, int i0sel,
                       const float* __restrict__ W, const float* __restrict__ bias,
                       float* __restrict__ ext_out, int osel) {
    constexpr int BM  = 128;
    constexpr int KD  = 4 * FIN;
    constexpr int NCH = KD / SK;
    constexpr int TN  = FOUT / 8;

    __shared__ float hs[BM][SK + 1];
    __shared__ float ws[SK][FOUT];

    const float* hb[4];
    hb[0] = (i0sel < 0) ? ext0 : g_nf.v[i0sel];
    hb[1] = g_nf.v[0];
    hb[2] = g_nf.v[1];
    hb[3] = g_nf.v[2];
    float* out = (osel < 0) ? ext_out : g_nf.v[osel];

    int row0 = blockIdx.x * BM;
    int tid  = threadIdx.x;
    int trow = tid >> 3;
    int tcol = tid & 7;
    int myrow = row0 + tid;

    float acc[8][TN];
#pragma unroll
    for (int m = 0; m < 8; m++)
#pragma unroll
        for (int n = 0; n < TN; n++) acc[m][n] = 0.f;

    for (int c = 0; c < NCH; c++) {
        int gi0 = c * SK;
        const float* hp = hb[gi0 / FIN];
        int off = gi0 % FIN;
        if (myrow < NN) {
            const float4* s4 = reinterpret_cast<const float4*>(hp + (size_t)myrow * FIN + off);
#pragma unroll
            for (int q = 0; q < SK / 4; q++) {
                float4 v = s4[q];
                hs[tid][q * 4 + 0] = v.x;
                hs[tid][q * 4 + 1] = v.y;
                hs[tid][q * 4 + 2] = v.z;
                hs[tid][q * 4 + 3] = v.w;
            }
        } else {
#pragma unroll
            for (int q = 0; q < SK; q++) hs[tid][q] = 0.f;
        }
        for (int idx = tid; idx < SK * FOUT; idx += BM)
            ((float*)ws)[idx] = W[gi0 * FOUT + idx];
        __syncthreads();

#pragma unroll
        for (int i = 0; i < SK; i++) {
            float hr[8];
#pragma unroll
            for (int m = 0; m < 8; m++) hr[m] = hs[trow * 8 + m][i];
            float wv[TN];
#pragma unroll
            for (int n = 0; n < TN; n++) wv[n] = ws[i][n * 8 + tcol];
#pragma unroll
            for (int m = 0; m < 8; m++)
#pragma unroll
                for (int n = 0; n < TN; n++)
                    acc[m][n] = fmaf(hr[m], wv[n], acc[m][n]);
        }
        __syncthreads();
    }

#pragma unroll
    for (int m = 0; m < 8; m++) {
        int r = row0 + trow * 8 + m;
        if (r < NN) {
#pragma unroll
            for (int n = 0; n < TN; n++) {
                int j = n * 8 + tcol;
                float v = acc[m][n] + bias[j];
                if (RELU) v = fmaxf(v, 0.f);
                out[(size_t)r * FOUT + j] = v;
            }
        }
    }
}

// ---------------- last-layer Y GEMM: Y[n][k*8+j] = sum_i h[n][i] * Wl[k][i][j] ------
// h: [NN x 64], Wl: [4][64][8] contiguous, Y: [NN x 32]
__global__ void k_gemmY(int isel, int osel, const float* __restrict__ Wl) {
    constexpr int BM = 128;
    constexpr int SK = 32;
    __shared__ float hs[BM][SK + 1];
    __shared__ float ws[SK][32];

    const float* __restrict__ h = g_nf.v[isel];
    float* __restrict__ Y = g_nf.v[osel];

    int row0 = blockIdx.x * BM;
    int tid  = threadIdx.x;
    int trow = tid >> 3;   // 0..15
    int tcol = tid & 7;    // 0..7
    int myrow = row0 + tid;

    float acc[8][4];
#pragma unroll
    for (int m = 0; m < 8; m++)
#pragma unroll
        for (int n = 0; n < 4; n++) acc[m][n] = 0.f;

    for (int c = 0; c < 2; c++) {
        int gi0 = c * SK;
        if (myrow < NN) {
            const float4* s4 = reinterpret_cast<const float4*>(h + (size_t)myrow * 64 + gi0);
#pragma unroll
            for (int q = 0; q < SK / 4; q++) {
                float4 v = s4[q];
                hs[tid][q * 4 + 0] = v.x;
                hs[tid][q * 4 + 1] = v.y;
                hs[tid][q * 4 + 2] = v.z;
                hs[tid][q * 4 + 3] = v.w;
            }
        } else {
#pragma unroll
            for (int q = 0; q < SK; q++) hs[tid][q] = 0.f;
        }
        // permuted W staging: ws[i][k*8+j] = Wl[k*512 + (gi0+i)*8 + j]
        for (int idx = tid; idx < SK * 32; idx += BM) {
            int il = idx >> 5, cc = idx & 31;
            int k = cc >> 3, j = cc & 7;
            ws[il][cc] = Wl[k * 512 + (gi0 + il) * 8 + j];
        }
        __syncthreads();

#pragma unroll
        for (int i = 0; i < SK; i++) {
            float hr[8];
#pragma unroll
            for (int m = 0; m < 8; m++) hr[m] = hs[trow * 8 + m][i];
            float wv[4];
#pragma unroll
            for (int n = 0; n < 4; n++) wv[n] = ws[i][n * 8 + tcol];
#pragma unroll
            for (int m = 0; m < 8; m++)
#pragma unroll
                for (int n = 0; n < 4; n++)
                    acc[m][n] = fmaf(hr[m], wv[n], acc[m][n]);
        }
        __syncthreads();
    }

#pragma unroll
    for (int m = 0; m < 8; m++) {
        int r = row0 + trow * 8 + m;
        if (r < NN) {
#pragma unroll
            for (int n = 0; n < 4; n++)
                Y[(size_t)r * 32 + n * 8 + tcol] = acc[m][n];
        }
    }
}

// ---------------- launch ----------------
extern "C" void kernel_launch(void* const* d_in, const int* in_sizes, int n_in,
                              void* d_out, int out_size) {
    const float* x  = (const float*)d_in[0];
    const int*   ei = (const int*)d_in[1];     // int32! (JAX x64 disabled)
    const float* ea = (const float*)d_in[2];
    const float* W1 = (const float*)d_in[3];
    const float* b1 = (const float*)d_in[4];
    const float* W2 = (const float*)d_in[5];
    const float* b2 = (const float*)d_in[6];
    const float* Wf = (const float*)d_in[7];
    const float* bf = (const float*)d_in[8];
    const float* Wm = (const float*)d_in[9];
    const float* bm = (const float*)d_in[10];
    const float* Wl = (const float*)d_in[11];
    const float* bl = (const float*)d_in[12];
    float*       out = (float*)d_out;

    const int NB_N   = (NN + 255) / 256;
    const int NB_E   = (NE + 255) / 256;
    const int NB_P64 = (NN * 32 + 255) / 256;
    const int NB_P16 = (NN * 16 + 255) / 256;
    const int NB_P8  = (NN * 8 + 255) / 256;
    const int NB_G   = (NN + 127) / 128;

    // preprocessing: edge weights, gcn norm (dinv in scan1), CSR build
    k_zero<<<NB_N, 256>>>();
    k_edge<<<NB_E, 256>>>(ea, ei, W1, b1, W2, b2);
    k_scan1<<<SCAN_NBLK, SCAN_B>>>();
    k_scan2<<<1, 32>>>();
    k_scan3<<<SCAN_NBLK, SCAN_B>>>();
    k_fill<<<NB_E, 256>>>(ei);

    // layer 0: FIN=16 -> 64, relu
    k_prop16<<<NB_P16, 256>>>(x, -1, 0);
    k_prop16<<<NB_P16, 256>>>(nullptr, 0, 1);
    k_prop16<<<NB_P16, 256>>>(nullptr, 1, 2);
    k_gemm<16, 64, 16, true><<<NB_G, 128>>>(x, -1, Wf, bf, nullptr, 3);

    // mid layer 0: 64 -> 64, relu
    k_prop64<<<NB_P64, 256>>>(3, 0);
    k_prop64<<<NB_P64, 256>>>(0, 1);
    k_prop64<<<NB_P64, 256>>>(1, 2);
    k_gemm<64, 64, 32, true><<<NB_G, 128>>>(nullptr, 3, Wm, bm, nullptr, 4);

    // mid layer 1: 64 -> 64, relu
    k_prop64<<<NB_P64, 256>>>(4, 0);
    k_prop64<<<NB_P64, 256>>>(0, 1);
    k_prop64<<<NB_P64, 256>>>(1, 2);
    k_gemm<64, 64, 32, true><<<NB_G, 128>>>(nullptr, 4, Wm + 4 * 64 * 64, bm + 64, nullptr, 3);

    // last layer via Horner: Y = h @ [W0|W1|W2|W3]  (N x 32), then 3 hops at F=8
    k_gemmY<<<NB_G, 128>>>(3, 4, Wl);
    // T1 = A*Y3 + Y2   (buf0)
    k_prop8<<<NB_P8, 256>>>(4, 24, 32, 4, 16, 32, nullptr, nullptr, 0);
    // T2 = A*T1 + Y1   (buf1)
    k_prop8<<<NB_P8, 256>>>(0, 0, 8, 4, 8, 32, nullptr, nullptr, 1);
    // out = A*T2 + Y0 + b
    k_prop8<<<NB_P8, 256>>>(1, 0, 8, 4, 0, 32, bl, out, -1);
}

// round 6
// speedup vs baseline: 1.3075x; 1.0143x over previous
#include <cuda_runtime.h>

#define NN 50000
#define NE 800000
#define SCAN_B 512
#define SCAN_NBLK ((NN + SCAN_B - 1) / SCAN_B)   // 98

// ---------------- packed f32x2 helpers (FFMA2 — only reachable via PTX) ----------------
__device__ __forceinline__ unsigned long long pk2(float a, float b) {
    unsigned long long r;
    asm("mov.b64 %0, {%1, %2};" : "=l"(r) : "f"(a), "f"(b));
    return r;
}
__device__ __forceinline__ void fma2(unsigned long long& d, unsigned long long a, unsigned long long b) {
    asm("fma.rn.f32x2 %0, %1, %2, %0;" : "+l"(d) : "l"(a), "l"(b));
}
__device__ __forceinline__ float2 upk2(unsigned long long v) {
    float2 r;
    asm("mov.b64 {%0, %1}, %2;" : "=f"(r.x), "=f"(r.y) : "l"(v));
    return r;
}

// ---------------- scratch (static device globals; no allocs) ----------------
__device__ float g_ew[NE];
__device__ float g_deg[NN];
__device__ float g_dinv[NN];
__device__ int   g_cnt[NN];
__device__ int   g_rowptr[NN + 1];
__device__ int   g_cur[NN];
__device__ int   g_csr_src[NE];
__device__ float g_csr_w[NE];
__device__ int   g_psum[SCAN_NBLK];
__device__ int   g_poff[SCAN_NBLK];
// 5 node-feature buffers of [NN x 64]: 0,1,2 = hop buffers, 3,4 = layer ping-pong
struct alignas(16) NFBuf { float v[5][NN * 64]; };
__device__ NFBuf g_nf;

// ---------------- init ----------------
__global__ void k_zero() {
    int i = blockIdx.x * blockDim.x + threadIdx.x;
    if (i < NN) { g_deg[i] = 0.f; g_cnt[i] = 0; }
}

// ---------------- edge MLP -> ew, plus deg & count histograms ----------------
// NOTE: edge_index is int32 (JAX x64 disabled downcasts jnp.int64 -> int32).
__global__ void k_edge(const float* __restrict__ ea, const int* __restrict__ ei,
                       const float* __restrict__ W1, const float* __restrict__ b1,
                       const float* __restrict__ W2, const float* __restrict__ b2) {
    __shared__ float sW1[512];
    __shared__ float sb1[64];
    __shared__ float sW2[64];
    __shared__ float sb2;
    for (int i = threadIdx.x; i < 512; i += blockDim.x) sW1[i] = W1[i];
    if (threadIdx.x < 64) { sb1[threadIdx.x] = b1[threadIdx.x]; sW2[threadIdx.x] = W2[threadIdx.x]; }
    if (threadIdx.x == 0) sb2 = b2[0];
    __syncthreads();

    int e = blockIdx.x * blockDim.x + threadIdx.x;
    if (e >= NE) return;

    float4 v0 = reinterpret_cast<const float4*>(ea)[e * 2];
    float4 v1 = reinterpret_cast<const float4*>(ea)[e * 2 + 1];
    float a[8] = {v0.x, v0.y, v0.z, v0.w, v1.x, v1.y, v1.z, v1.w};
    unsigned long long ad[8];
#pragma unroll
    for (int i = 0; i < 8; i++) ad[i] = pk2(a[i], a[i]);

    float ew = sb2;
#pragma unroll 8
    for (int j = 0; j < 64; j += 2) {
        unsigned long long h2 = pk2(sb1[j], sb1[j + 1]);
#pragma unroll
        for (int i = 0; i < 8; i++) {
            unsigned long long w2 = *reinterpret_cast<const unsigned long long*>(&sW1[i * 64 + j]);
            fma2(h2, ad[i], w2);
        }
        float2 h = upk2(h2);
        ew = fmaf(fmaxf(h.x, 0.f), sW2[j],     ew);
        ew = fmaf(fmaxf(h.y, 0.f), sW2[j + 1], ew);
    }
    g_ew[e] = ew;
    int dst = ei[NE + e];
    atomicAdd(&g_deg[dst], ew);
    atomicAdd(&g_cnt[dst], 1);
}

// ---------------- multi-block scan over counts -> rowptr ----------------
// pass 1: per-block reduction of counts; also compute dinv (deg already final)
__global__ void k_scan1() {
    __shared__ int red[SCAN_B / 32];
    int b = blockIdx.x, t = threadIdx.x;
    int i = b * SCAN_B + t;
    int c = (i < NN) ? g_cnt[i] : 0;
    if (i < NN) {
        float d = g_deg[i];
        g_dinv[i] = (d > 0.f) ? rsqrtf(d) : 0.f;
    }
    int v = c;
#pragma unroll
    for (int o = 16; o; o >>= 1) v += __shfl_down_sync(0xffffffffu, v, o);
    if ((t & 31) == 0) red[t >> 5] = v;
    __syncthreads();
    if (t == 0) {
        int s = 0;
#pragma unroll
        for (int w = 0; w < SCAN_B / 32; w++) s += red[w];
        g_psum[b] = s;
    }
}
// pass 2: parallel exclusive scan over 98 block sums (128 threads, Hillis-Steele)
__global__ void k_scan2() {
    __shared__ int sc[128];
    int t = threadIdx.x;
    int c = (t < SCAN_NBLK) ? g_psum[t] : 0;
    sc[t] = c;
    __syncthreads();
#pragma unroll
    for (int off = 1; off < 128; off <<= 1) {
        int v = (t >= off) ? sc[t - off] : 0;
        __syncthreads();
        sc[t] += v;
        __syncthreads();
    }
    if (t < SCAN_NBLK) g_poff[t] = sc[t] - c;
    if (t == 127) g_rowptr[NN] = sc[127];   // == NE
}
// pass 3: per-block exclusive scan + global offset -> rowptr, cur
__global__ void k_scan3() {
    __shared__ int sc[SCAN_B];
    int b = blockIdx.x, t = threadIdx.x;
    int i = b * SCAN_B + t;
    int c = (i < NN) ? g_cnt[i] : 0;
    sc[t] = c;
    __syncthreads();
#pragma unroll
    for (int off = 1; off < SCAN_B; off <<= 1) {
        int v = (t >= off) ? sc[t - off] : 0;
        __syncthreads();
        sc[t] += v;
        __syncthreads();
    }
    if (i < NN) {
        int excl = sc[t] - c + g_poff[b];
        g_rowptr[i] = excl;
        g_cur[i]    = excl;
    }
}

// ---------------- fill CSR (by dst) with fused normalized weight ----------------
__global__ void k_fill(const int* __restrict__ ei) {
    int e = blockIdx.x * blockDim.x + threadIdx.x;
    if (e >= NE) return;
    int src = ei[e];
    int dst = ei[NE + e];
    float w = g_dinv[src] * g_ew[e] * g_dinv[dst];
    int pos = atomicAdd(&g_cur[dst], 1);
    g_csr_src[pos] = src;
    g_csr_w[pos]   = w;
}

// ---------------- propagation: h_out[n] = sum_{e->n} w_e * h_in[src_e] ----------------
// F=64: one warp per node, 2 features per lane
__global__ void k_prop64(int isel, int osel) {
    int g    = blockIdx.x * blockDim.x + threadIdx.x;
    int node = g >> 5;
    int lane = g & 31;
    if (node >= NN) return;
    const float* __restrict__ hin  = g_nf.v[isel];
    float* __restrict__       hout = g_nf.v[osel];
    int beg = g_rowptr[node], end = g_rowptr[node + 1];
    float acc0 = 0.f, acc1 = 0.f;
    int p = beg;
    for (; p + 1 < end; p += 2) {
        int   s0 = g_csr_src[p],     s1 = g_csr_src[p + 1];
        float w0 = g_csr_w[p],       w1 = g_csr_w[p + 1];
        const float* r0 = hin + (size_t)s0 * 64;
        const float* r1 = hin + (size_t)s1 * 64;
        float x0 = __ldg(r0 + lane), y0 = __ldg(r0 + lane + 32);
        float x1 = __ldg(r1 + lane), y1 = __ldg(r1 + lane + 32);
        acc0 = fmaf(w0, x0, acc0); acc1 = fmaf(w0, y0, acc1);
        acc0 = fmaf(w1, x1, acc0); acc1 = fmaf(w1, y1, acc1);
    }
    if (p < end) {
        int s = g_csr_src[p];
        float w = g_csr_w[p];
        const float* r = hin + (size_t)s * 64;
        acc0 = fmaf(w, __ldg(r + lane),      acc0);
        acc1 = fmaf(w, __ldg(r + lane + 32), acc1);
    }
    hout[(size_t)node * 64 + lane]      = acc0;
    hout[(size_t)node * 64 + lane + 32] = acc1;
}

// F=16: 16 threads per node (2 nodes per warp)
__global__ void k_prop16(const float* __restrict__ ext, int isel, int osel) {
    int g    = blockIdx.x * blockDim.x + threadIdx.x;
    int node = g >> 4;
    int f    = g & 15;
    if (node >= NN) return;
    const float* __restrict__ hin  = (isel < 0) ? ext : g_nf.v[isel];
    float* __restrict__       hout = g_nf.v[osel];
    int beg = g_rowptr[node], end = g_rowptr[node + 1];
    float acc = 0.f;
    for (int p = beg; p < end; p++) {
        acc = fmaf(g_csr_w[p], __ldg(hin + (size_t)g_csr_src[p] * 16 + f), acc);
    }
    hout[(size_t)node * 16 + f] = acc;
}

// F=8 Horner hop: out[n] = (A tin)[n] + yadd[n] (+ bias). out stride fixed = 8.
__global__ void k_prop8(int tin_sel, int tin_off, int tin_stride,
                        int y_sel, int y_off, int y_stride,
                        const float* __restrict__ bias,
                        float* __restrict__ ext_out, int out_sel) {
    int g    = blockIdx.x * blockDim.x + threadIdx.x;
    int node = g >> 3;
    int f    = g & 7;
    if (node >= NN) return;
    const float* __restrict__ tin = g_nf.v[tin_sel] + tin_off;
    const float* __restrict__ ya  = g_nf.v[y_sel]  + y_off;
    float* __restrict__ outp = ext_out ? ext_out : g_nf.v[out_sel];
    int beg = g_rowptr[node], end = g_rowptr[node + 1];
    float acc0 = 0.f, acc1 = 0.f;
    int p = beg;
    for (; p + 1 < end; p += 2) {
        int   s0 = g_csr_src[p],  s1 = g_csr_src[p + 1];
        float w0 = g_csr_w[p],    w1 = g_csr_w[p + 1];
        acc0 = fmaf(w0, __ldg(tin + (size_t)s0 * tin_stride + f), acc0);
        acc1 = fmaf(w1, __ldg(tin + (size_t)s1 * tin_stride + f), acc1);
    }
    if (p < end)
        acc0 = fmaf(g_csr_w[p], __ldg(tin + (size_t)g_csr_src[p] * tin_stride + f), acc0);
    float v = acc0 + acc1 + ya[(size_t)node * y_stride + f];
    if (bias) v += bias[f];
    outp[(size_t)node * 8 + f] = v;
}

// ---------------- fused TAGConv GEMM (f32x2 packed): out = [h0|h1|h2|h3] @ W + b -----
// BM=128 rows/block, 128 threads; thread = 8 rows x TN contiguous cols.
// hst is TRANSPOSED so hr loads are LDS.128; cols contiguous so wv loads are LDS.128.
template <int FIN, int FOUT, int SK, bool RELU>
__global__ void k_gemm(const float* __restrict__ ext0, int i0sel,
                       const float* __restrict__ W, const float* __restrict__ bias,
                       float* __restrict__ ext_out, int osel) {
    constexpr int BM  = 128;
    constexpr int KD  = 4 * FIN;
    constexpr int NCH = KD / SK;
    constexpr int TN  = FOUT / 8;       // contiguous cols per thread (8 or 1*... >=2, even)
    constexpr int TP  = TN / 2;         // f32x2 pairs per thread

    __shared__ float hst[SK][BM];       // transposed h tile
    __shared__ float ws[SK][FOUT];

    const float* hb[4];
    hb[0] = (i0sel < 0) ? ext0 : g_nf.v[i0sel];
    hb[1] = g_nf.v[0];
    hb[2] = g_nf.v[1];
    hb[3] = g_nf.v[2];
    float* out = (osel < 0) ? ext_out : g_nf.v[osel];

    int row0 = blockIdx.x * BM;
    int tid  = threadIdx.x;
    int trow = tid >> 3;                // 0..15 -> rows trow*8..+8
    int tcol = tid & 7;                 // cols tcol*TN..+TN
    int myrow = row0 + tid;

    unsigned long long acc[8][TP];
#pragma unroll
    for (int m = 0; m < 8; m++)
#pragma unroll
        for (int n = 0; n < TP; n++) acc[m][n] = 0ull;

    for (int c = 0; c < NCH; c++) {
        int gi0 = c * SK;
        const float* hp = hb[gi0 / FIN];
        int off = gi0 % FIN;
        // stage transposed h tile
        if (myrow < NN) {
            const float4* s4 = reinterpret_cast<const float4*>(hp + (size_t)myrow * FIN + off);
#pragma unroll
            for (int q = 0; q < SK / 4; q++) {
                float4 v = s4[q];
                hst[q * 4 + 0][tid] = v.x;
                hst[q * 4 + 1][tid] = v.y;
                hst[q * 4 + 2][tid] = v.z;
                hst[q * 4 + 3][tid] = v.w;
            }
        } else {
#pragma unroll
            for (int q = 0; q < SK; q++) hst[q][tid] = 0.f;
        }
        // stage W tile (contiguous)
        for (int idx = tid; idx < SK * FOUT; idx += BM)
            ((float*)ws)[idx] = W[gi0 * FOUT + idx];
        __syncthreads();

#pragma unroll
        for (int i = 0; i < SK; i++) {
            // 8 row values (2x LDS.128, broadcast across tcol lanes)
            float4 ha = *reinterpret_cast<const float4*>(&hst[i][trow * 8]);
            float4 hc = *reinterpret_cast<const float4*>(&hst[i][trow * 8 + 4]);
            unsigned long long hd[8];
            hd[0] = pk2(ha.x, ha.x); hd[1] = pk2(ha.y, ha.y);
            hd[2] = pk2(ha.z, ha.z); hd[3] = pk2(ha.w, ha.w);
            hd[4] = pk2(hc.x, hc.x); hd[5] = pk2(hc.y, hc.y);
            hd[6] = pk2(hc.z, hc.z); hd[7] = pk2(hc.w, hc.w);
            // TN contiguous col weights as f32x2 pairs
            unsigned long long wv[TP];
#pragma unroll
            for (int q = 0; q < TP / 2; q++) {
                float4 w4 = *reinterpret_cast<const float4*>(&ws[i][tcol * TN + q * 4]);
                wv[q * 2]     = pk2(w4.x, w4.y);
                wv[q * 2 + 1] = pk2(w4.z, w4.w);
            }
            if (TP & 1) {
                float2 w2 = *reinterpret_cast<const float2*>(&ws[i][tcol * TN + (TP - 1) * 2]);
                wv[TP - 1] = pk2(w2.x, w2.y);
            }
#pragma unroll
            for (int m = 0; m < 8; m++)
#pragma unroll
                for (int n = 0; n < TP; n++)
                    fma2(acc[m][n], hd[m], wv[n]);
        }
        __syncthreads();
    }

#pragma unroll
    for (int m = 0; m < 8; m++) {
        int r = row0 + trow * 8 + m;
        if (r < NN) {
#pragma unroll
            for (int n = 0; n < TP; n++) {
                float2 v = upk2(acc[m][n]);
                int j = tcol * TN + n * 2;
                float o0 = v.x + bias[j];
                float o1 = v.y + bias[j + 1];
                if (RELU) { o0 = fmaxf(o0, 0.f); o1 = fmaxf(o1, 0.f); }
                out[(size_t)r * FOUT + j]     = o0;
                out[(size_t)r * FOUT + j + 1] = o1;
            }
        }
    }
}

// ---------------- last-layer Y GEMM (f32x2): Y[n][k*8+j] = sum_i h[n][i]*Wl[k][i][j] --
// h: [NN x 64], Wl: [4][64][8], Y: [NN x 32]. Thread = 8 rows x 4 contiguous cols.
__global__ void k_gemmY(int isel, int osel, const float* __restrict__ Wl) {
    constexpr int BM = 128;
    constexpr int SK = 32;
    __shared__ float hst[SK][BM];
    __shared__ float ws[SK][32];

    const float* __restrict__ h = g_nf.v[isel];
    float* __restrict__ Y = g_nf.v[osel];

    int row0 = blockIdx.x * BM;
    int tid  = threadIdx.x;
    int trow = tid >> 3;   // 0..15
    int tcol = tid & 7;    // cols tcol*4..+4
    int myrow = row0 + tid;

    unsigned long long acc[8][2];
#pragma unroll
    for (int m = 0; m < 8; m++) { acc[m][0] = 0ull; acc[m][1] = 0ull; }

    for (int c = 0; c < 2; c++) {
        int gi0 = c * SK;
        if (myrow < NN) {
            const float4* s4 = reinterpret_cast<const float4*>(h + (size_t)myrow * 64 + gi0);
#pragma unroll
            for (int q = 0; q < SK / 4; q++) {
                float4 v = s4[q];
                hst[q * 4 + 0][tid] = v.x;
                hst[q * 4 + 1][tid] = v.y;
                hst[q * 4 + 2][tid] = v.z;
                hst[q * 4 + 3][tid] = v.w;
            }
        } else {
#pragma unroll
            for (int q = 0; q < SK; q++) hst[q][tid] = 0.f;
        }
        // permuted W staging: ws[i][k*8+j] = Wl[k*512 + (gi0+i)*8 + j]
        for (int idx = tid; idx < SK * 32; idx += BM) {
            int il = idx >> 5, cc = idx & 31;
            int k = cc >> 3, j = cc & 7;
            ws[il][cc] = Wl[k * 512 + (gi0 + il) * 8 + j];
        }
        __syncthreads();

#pragma unroll
        for (int i = 0; i < SK; i++) {
            float4 ha = *reinterpret_cast<const float4*>(&hst[i][trow * 8]);
            float4 hc = *reinterpret_cast<const float4*>(&hst[i][trow * 8 + 4]);
            unsigned long long hd[8];
            hd[0] = pk2(ha.x, ha.x); hd[1] = pk2(ha.y, ha.y);
            hd[2] = pk2(ha.z, ha.z); hd[3] = pk2(ha.w, ha.w);
            hd[4] = pk2(hc.x, hc.x); hd[5] = pk2(hc.y, hc.y);
            hd[6] = pk2(hc.z, hc.z); hd[7] = pk2(hc.w, hc.w);
            float4 w4 = *reinterpret_cast<const float4*>(&ws[i][tcol * 4]);
            unsigned long long wv0 = pk2(w4.x, w4.y);
            unsigned long long wv1 = pk2(w4.z, w4.w);
#pragma unroll
            for (int m = 0; m < 8; m++) {
                fma2(acc[m][0], hd[m], wv0);
                fma2(acc[m][1], hd[m], wv1);
            }
        }
        __syncthreads();
    }

#pragma unroll
    for (int m = 0; m < 8; m++) {
        int r = row0 + trow * 8 + m;
        if (r < NN) {
            float2 v0 = upk2(acc[m][0]);
            float2 v1 = upk2(acc[m][1]);
            float4 o = make_float4(v0.x, v0.y, v1.x, v1.y);
            *reinterpret_cast<float4*>(&Y[(size_t)r * 32 + tcol * 4]) = o;
        }
    }
}

// ---------------- launch ----------------
extern "C" void kernel_launch(void* const* d_in, const int* in_sizes, int n_in,
                              void* d_out, int out_size) {
    const float* x  = (const float*)d_in[0];
    const int*   ei = (const int*)d_in[1];     // int32! (JAX x64 disabled)
    const float* ea = (const float*)d_in[2];
    const float* W1 = (const float*)d_in[3];
    const float* b1 = (const float*)d_in[4];
    const float* W2 = (const float*)d_in[5];
    const float* b2 = (const float*)d_in[6];
    const float* Wf = (const float*)d_in[7];
    const float* bf = (const float*)d_in[8];
    const float* Wm = (const float*)d_in[9];
    const float* bm = (const float*)d_in[10];
    const float* Wl = (const float*)d_in[11];
    const float* bl = (const float*)d_in[12];
    float*       out = (float*)d_out;

    const int NB_N   = (NN + 255) / 256;
    const int NB_E   = (NE + 255) / 256;
    const int NB_P64 = (NN * 32 + 255) / 256;
    const int NB_P16 = (NN * 16 + 255) / 256;
    const int NB_P8  = (NN * 8 + 255) / 256;
    const int NB_G   = (NN + 127) / 128;

    // preprocessing: edge weights, gcn norm (dinv in scan1), CSR build
    k_zero<<<NB_N, 256>>>();
    k_edge<<<NB_E, 256>>>(ea, ei, W1, b1, W2, b2);
    k_scan1<<<SCAN_NBLK, SCAN_B>>>();
    k_scan2<<<1, 128>>>();
    k_scan3<<<SCAN_NBLK, SCAN_B>>>();
    k_fill<<<NB_E, 256>>>(ei);

    // layer 0: FIN=16 -> 64, relu
    k_prop16<<<NB_P16, 256>>>(x, -1, 0);
    k_prop16<<<NB_P16, 256>>>(nullptr, 0, 1);
    k_prop16<<<NB_P16, 256>>>(nullptr, 1, 2);
    k_gemm<16, 64, 16, true><<<NB_G, 128>>>(x, -1, Wf, bf, nullptr, 3);

    // mid layer 0: 64 -> 64, relu
    k_prop64<<<NB_P64, 256>>>(3, 0);
    k_prop64<<<NB_P64, 256>>>(0, 1);
    k_prop64<<<NB_P64, 256>>>(1, 2);
    k_gemm<64, 64, 32, true><<<NB_G, 128>>>(nullptr, 3, Wm, bm, nullptr, 4);

    // mid layer 1: 64 -> 64, relu
    k_prop64<<<NB_P64, 256>>>(4, 0);
    k_prop64<<<NB_P64, 256>>>(0, 1);
    k_prop64<<<NB_P64, 256>>>(1, 2);
    k_gemm<64, 64, 32, true><<<NB_G, 128>>>(nullptr, 4, Wm + 4 * 64 * 64, bm + 64, nullptr, 3);

    // last layer via Horner: Y = h @ [W0|W1|W2|W3]  (N x 32), then 3 hops at F=8
    k_gemmY<<<NB_G, 128>>>(3, 4, Wl);
    // T1 = A*Y3 + Y2   (buf0)
    k_prop8<<<NB_P8, 256>>>(4, 24, 32, 4, 16, 32, nullptr, nullptr, 0);
    // T2 = A*T1 + Y1   (buf1)
    k_prop8<<<NB_P8, 256>>>(0, 0, 8, 4, 8, 32, nullptr, nullptr, 1);
    // out = A*T2 + Y0 + b
    k_prop8<<<NB_P8, 256>>>(1, 0, 8, 4, 0, 32, bl, out, -1);
}

// round 7
// speedup vs baseline: 1.4255x; 1.0902x over previous
#include <cuda_runtime.h>
#include <cuda_fp16.h>

#define NN 50000
#define NE 800000
#define SCAN_B 512
#define SCAN_NBLK ((NN + SCAN_B - 1) / SCAN_B)   // 98

// ---------------- packed f32x2 helpers (FFMA2 — only reachable via PTX) ----------------
__device__ __forceinline__ unsigned long long pk2(float a, float b) {
    unsigned long long r;
    asm("mov.b64 %0, {%1, %2};" : "=l"(r) : "f"(a), "f"(b));
    return r;
}
__device__ __forceinline__ void fma2(unsigned long long& d, unsigned long long a, unsigned long long b) {
    asm("fma.rn.f32x2 %0, %1, %2, %0;" : "+l"(d) : "l"(a), "l"(b));
}
__device__ __forceinline__ float2 upk2(unsigned long long v) {
    float2 r;
    asm("mov.b64 {%0, %1}, %2;" : "=f"(r.x), "=f"(r.y) : "l"(v));
    return r;
}

// ---------------- scratch (static device globals; no allocs) ----------------
__device__ float g_ew[NE];
__device__ float g_deg[NN];
__device__ float g_dinv[NN];
__device__ int   g_cnt[NN];
__device__ int   g_rowptr[NN + 1];
__device__ int   g_cur[NN];
__device__ int   g_csr_src[NE];
__device__ float g_csr_w[NE];
__device__ int   g_psum[SCAN_NBLK];
__device__ int   g_poff[SCAN_NBLK];
// 5 node-feature fp32 buffers of [NN x 64]: 0,1,2 = hop buffers, 3,4 = layer ping-pong
struct alignas(16) NFBuf { float v[5][NN * 64]; };
__device__ NFBuf g_nf;
// 2 fp16 gather buffers [NN x 32 half2] (= NN x 64 feats), ping-pong inside a layer
struct alignas(16) NHBuf { __half2 v[2][NN * 32]; };
__device__ NHBuf g_nh;

// ---------------- init ----------------
__global__ void k_zero() {
    int i = blockIdx.x * blockDim.x + threadIdx.x;
    if (i < NN) { g_deg[i] = 0.f; g_cnt[i] = 0; }
}

// ---------------- edge MLP -> ew, plus deg & count histograms ----------------
// NOTE: edge_index is int32 (JAX x64 disabled downcasts jnp.int64 -> int32).
__global__ void k_edge(const float* __restrict__ ea, const int* __restrict__ ei,
                       const float* __restrict__ W1, const float* __restrict__ b1,
                       const float* __restrict__ W2, const float* __restrict__ b2) {
    __shared__ float sW1[512];
    __shared__ float sb1[64];
    __shared__ float sW2[64];
    __shared__ float sb2;
    for (int i = threadIdx.x; i < 512; i += blockDim.x) sW1[i] = W1[i];
    if (threadIdx.x < 64) { sb1[threadIdx.x] = b1[threadIdx.x]; sW2[threadIdx.x] = W2[threadIdx.x]; }
    if (threadIdx.x == 0) sb2 = b2[0];
    __syncthreads();

    int e = blockIdx.x * blockDim.x + threadIdx.x;
    if (e >= NE) return;

    float4 v0 = reinterpret_cast<const float4*>(ea)[e * 2];
    float4 v1 = reinterpret_cast<const float4*>(ea)[e * 2 + 1];
    float a[8] = {v0.x, v0.y, v0.z, v0.w, v1.x, v1.y, v1.z, v1.w};
    unsigned long long ad[8];
#pragma unroll
    for (int i = 0; i < 8; i++) ad[i] = pk2(a[i], a[i]);

    float ew = sb2;
#pragma unroll 8
    for (int j = 0; j < 64; j += 2) {
        unsigned long long h2 = pk2(sb1[j], sb1[j + 1]);
#pragma unroll
        for (int i = 0; i < 8; i++) {
            unsigned long long w2 = *reinterpret_cast<const unsigned long long*>(&sW1[i * 64 + j]);
            fma2(h2, ad[i], w2);
        }
        float2 h = upk2(h2);
        ew = fmaf(fmaxf(h.x, 0.f), sW2[j],     ew);
        ew = fmaf(fmaxf(h.y, 0.f), sW2[j + 1], ew);
    }
    g_ew[e] = ew;
    int dst = ei[NE + e];
    atomicAdd(&g_deg[dst], ew);
    atomicAdd(&g_cnt[dst], 1);
}

// ---------------- multi-block scan over counts -> rowptr ----------------
__global__ void k_scan1() {
    __shared__ int red[SCAN_B / 32];
    int b = blockIdx.x, t = threadIdx.x;
    int i = b * SCAN_B + t;
    int c = (i < NN) ? g_cnt[i] : 0;
    if (i < NN) {
        float d = g_deg[i];
        g_dinv[i] = (d > 0.f) ? rsqrtf(d) : 0.f;
    }
    int v = c;
#pragma unroll
    for (int o = 16; o; o >>= 1) v += __shfl_down_sync(0xffffffffu, v, o);
    if ((t & 31) == 0) red[t >> 5] = v;
    __syncthreads();
    if (t == 0) {
        int s = 0;
#pragma unroll
        for (int w = 0; w < SCAN_B / 32; w++) s += red[w];
        g_psum[b] = s;
    }
}
__global__ void k_scan2() {
    __shared__ int sc[128];
    int t = threadIdx.x;
    int c = (t < SCAN_NBLK) ? g_psum[t] : 0;
    sc[t] = c;
    __syncthreads();
#pragma unroll
    for (int off = 1; off < 128; off <<= 1) {
        int v = (t >= off) ? sc[t - off] : 0;
        __syncthreads();
        sc[t] += v;
        __syncthreads();
    }
    if (t < SCAN_NBLK) g_poff[t] = sc[t] - c;
    if (t == 127) g_rowptr[NN] = sc[127];   // == NE
}
__global__ void k_scan3() {
    __shared__ int sc[SCAN_B];
    int b = blockIdx.x, t = threadIdx.x;
    int i = b * SCAN_B + t;
    int c = (i < NN) ? g_cnt[i] : 0;
    sc[t] = c;
    __syncthreads();
#pragma unroll
    for (int off = 1; off < SCAN_B; off <<= 1) {
        int v = (t >= off) ? sc[t - off] : 0;
        __syncthreads();
        sc[t] += v;
        __syncthreads();
    }
    if (i < NN) {
        int excl = sc[t] - c + g_poff[b];
        g_rowptr[i] = excl;
        g_cur[i]    = excl;
    }
}

// ---------------- fill CSR (by dst) with fused normalized weight ----------------
__global__ void k_fill(const int* __restrict__ ei) {
    int e = blockIdx.x * blockDim.x + threadIdx.x;
    if (e >= NE) return;
    int src = ei[e];
    int dst = ei[NE + e];
    float w = g_dinv[src] * g_ew[e] * g_dinv[dst];
    int pos = atomicAdd(&g_cur[dst], 1);
    g_csr_src[pos] = src;
    g_csr_w[pos]   = w;
}

// ---------------- F=64 fp16-gather hop ----------------
// warp per node; lane owns half2 index `lane` (feats 2*lane, 2*lane+1).
// reads fp16 rows (128B/edge), accumulates fp32, writes fp32 (GEMM input) and
// optionally fp16 (next hop's gather input).
__global__ void k_prop64h(int hin_idx, int hout_idx, int fsel) {
    int g    = blockIdx.x * blockDim.x + threadIdx.x;
    int node = g >> 5;
    int lane = g & 31;
    if (node >= NN) return;
    const __half2* __restrict__ hin = g_nh.v[hin_idx];
    float* __restrict__ fout = g_nf.v[fsel];
    int beg = g_rowptr[node], end = g_rowptr[node + 1];
    float accx = 0.f, accy = 0.f;
    int p = beg;
    for (; p + 1 < end; p += 2) {
        int   s0 = g_csr_src[p],  s1 = g_csr_src[p + 1];
        float w0 = g_csr_w[p],    w1 = g_csr_w[p + 1];
        float2 f0 = __half22float2(hin[(size_t)s0 * 32 + lane]);
        float2 f1 = __half22float2(hin[(size_t)s1 * 32 + lane]);
        accx = fmaf(w0, f0.x, accx); accy = fmaf(w0, f0.y, accy);
        accx = fmaf(w1, f1.x, accx); accy = fmaf(w1, f1.y, accy);
    }
    if (p < end) {
        float w = g_csr_w[p];
        float2 f = __half22float2(hin[(size_t)g_csr_src[p] * 32 + lane]);
        accx = fmaf(w, f.x, accx); accy = fmaf(w, f.y, accy);
    }
    reinterpret_cast<float2*>(fout + (size_t)node * 64)[lane] = make_float2(accx, accy);
    if (hout_idx >= 0)
        g_nh.v[hout_idx][(size_t)node * 32 + lane] = __floats2half2_rn(accx, accy);
}

// F=16: 16 threads per node (fp32, layer 0 only)
__global__ void k_prop16(const float* __restrict__ ext, int isel, int osel) {
    int g    = blockIdx.x * blockDim.x + threadIdx.x;
    int node = g >> 4;
    int f    = g & 15;
    if (node >= NN) return;
    const float* __restrict__ hin  = (isel < 0) ? ext : g_nf.v[isel];
    float* __restrict__       hout = g_nf.v[osel];
    int beg = g_rowptr[node], end = g_rowptr[node + 1];
    float acc = 0.f;
    for (int p = beg; p < end; p++) {
        acc = fmaf(g_csr_w[p], __ldg(hin + (size_t)g_csr_src[p] * 16 + f), acc);
    }
    hout[(size_t)node * 16 + f] = acc;
}

// F=8 Horner hop (fp32, last layer): out[n] = (A tin)[n] + yadd[n] (+ bias)
__global__ void k_prop8(int tin_sel, int tin_off, int tin_stride,
                        int y_sel, int y_off, int y_stride,
                        const float* __restrict__ bias,
                        float* __restrict__ ext_out, int out_sel) {
    int g    = blockIdx.x * blockDim.x + threadIdx.x;
    int node = g >> 3;
    int f    = g & 7;
    if (node >= NN) return;
    const float* __restrict__ tin = g_nf.v[tin_sel] + tin_off;
    const float* __restrict__ ya  = g_nf.v[y_sel]  + y_off;
    float* __restrict__ outp = ext_out ? ext_out : g_nf.v[out_sel];
    int beg = g_rowptr[node], end = g_rowptr[node + 1];
    float acc0 = 0.f, acc1 = 0.f;
    int p = beg;
    for (; p + 1 < end; p += 2) {
        int   s0 = g_csr_src[p],  s1 = g_csr_src[p + 1];
        float w0 = g_csr_w[p],    w1 = g_csr_w[p + 1];
        acc0 = fmaf(w0, __ldg(tin + (size_t)s0 * tin_stride + f), acc0);
        acc1 = fmaf(w1, __ldg(tin + (size_t)s1 * tin_stride + f), acc1);
    }
    if (p < end)
        acc0 = fmaf(g_csr_w[p], __ldg(tin + (size_t)g_csr_src[p] * tin_stride + f), acc0);
    float v = acc0 + acc1 + ya[(size_t)node * y_stride + f];
    if (bias) v += bias[f];
    outp[(size_t)node * 8 + f] = v;
}

// ---------------- fused TAGConv GEMM (f32x2 packed) ----------------
// out = [h0|h1|h2|h3] @ W + b (opt relu); optionally also emits fp16 copy of out
// (the gather seed for the next layer's hop chain).
template <int FIN, int FOUT, int SK, bool RELU, bool HC>
__global__ void k_gemm(const float* __restrict__ ext0, int i0sel,
                       const float* __restrict__ W, const float* __restrict__ bias,
                       float* __restrict__ ext_out, int osel, int hcopy_idx) {
    constexpr int BM  = 128;
    constexpr int KD  = 4 * FIN;
    constexpr int NCH = KD / SK;
    constexpr int TN  = FOUT / 8;
    constexpr int TP  = TN / 2;

    __shared__ float hst[SK][BM];       // transposed h tile
    __shared__ float ws[SK][FOUT];

    const float* hb[4];
    hb[0] = (i0sel < 0) ? ext0 : g_nf.v[i0sel];
    hb[1] = g_nf.v[0];
    hb[2] = g_nf.v[1];
    hb[3] = g_nf.v[2];
    float* out = (osel < 0) ? ext_out : g_nf.v[osel];
    __half2* hcp = HC ? g_nh.v[hcopy_idx] : nullptr;

    int row0 = blockIdx.x * BM;
    int tid  = threadIdx.x;
    int trow = tid >> 3;
    int tcol = tid & 7;
    int myrow = row0 + tid;

    unsigned long long acc[8][TP];
#pragma unroll
    for (int m = 0; m < 8; m++)
#pragma unroll
        for (int n = 0; n < TP; n++) acc[m][n] = 0ull;

    for (int c = 0; c < NCH; c++) {
        int gi0 = c * SK;
        const float* hp = hb[gi0 / FIN];
        int off = gi0 % FIN;
        if (myrow < NN) {
            const float4* s4 = reinterpret_cast<const float4*>(hp + (size_t)myrow * FIN + off);
#pragma unroll
            for (int q = 0; q < SK / 4; q++) {
                float4 v = s4[q];
                hst[q * 4 + 0][tid] = v.x;
                hst[q * 4 + 1][tid] = v.y;
                hst[q * 4 + 2][tid] = v.z;
                hst[q * 4 + 3][tid] = v.w;
            }
        } else {
#pragma unroll
            for (int q = 0; q < SK; q++) hst[q][tid] = 0.f;
        }
        for (int idx = tid; idx < SK * FOUT; idx += BM)
            ((float*)ws)[idx] = W[gi0 * FOUT + idx];
        __syncthreads();

#pragma unroll
        for (int i = 0; i < SK; i++) {
            float4 ha = *reinterpret_cast<const float4*>(&hst[i][trow * 8]);
            float4 hc = *reinterpret_cast<const float4*>(&hst[i][trow * 8 + 4]);
            unsigned long long hd[8];
            hd[0] = pk2(ha.x, ha.x); hd[1] = pk2(ha.y, ha.y);
            hd[2] = pk2(ha.z, ha.z); hd[3] = pk2(ha.w, ha.w);
            hd[4] = pk2(hc.x, hc.x); hd[5] = pk2(hc.y, hc.y);
            hd[6] = pk2(hc.z, hc.z); hd[7] = pk2(hc.w, hc.w);
            unsigned long long wv[TP];
#pragma unroll
            for (int q = 0; q < TP / 2; q++) {
                float4 w4 = *reinterpret_cast<const float4*>(&ws[i][tcol * TN + q * 4]);
                wv[q * 2]     = pk2(w4.x, w4.y);
                wv[q * 2 + 1] = pk2(w4.z, w4.w);
            }
            if (TP & 1) {
                float2 w2 = *reinterpret_cast<const float2*>(&ws[i][tcol * TN + (TP - 1) * 2]);
                wv[TP - 1] = pk2(w2.x, w2.y);
            }
#pragma unroll
            for (int m = 0; m < 8; m++)
#pragma unroll
                for (int n = 0; n < TP; n++)
                    fma2(acc[m][n], hd[m], wv[n]);
        }
        __syncthreads();
    }

#pragma unroll
    for (int m = 0; m < 8; m++) {
        int r = row0 + trow * 8 + m;
        if (r < NN) {
#pragma unroll
            for (int n = 0; n < TP; n++) {
                float2 v = upk2(acc[m][n]);
                int j = tcol * TN + n * 2;
                float o0 = v.x + bias[j];
                float o1 = v.y + bias[j + 1];
                if (RELU) { o0 = fmaxf(o0, 0.f); o1 = fmaxf(o1, 0.f); }
                out[(size_t)r * FOUT + j]     = o0;
                out[(size_t)r * FOUT + j + 1] = o1;
                if (HC) hcp[(size_t)r * 32 + (j >> 1)] = __floats2half2_rn(o0, o1);
            }
        }
    }
}

// ---------------- last-layer Y GEMM (f32x2): Y[n][k*8+j] = sum_i h[n][i]*Wl[k][i][j] --
__global__ void k_gemmY(int isel, int osel, const float* __restrict__ Wl) {
    constexpr int BM = 128;
    constexpr int SK = 32;
    __shared__ float hst[SK][BM];
    __shared__ float ws[SK][32];

    const float* __restrict__ h = g_nf.v[isel];
    float* __restrict__ Y = g_nf.v[osel];

    int row0 = blockIdx.x * BM;
    int tid  = threadIdx.x;
    int trow = tid >> 3;
    int tcol = tid & 7;
    int myrow = row0 + tid;

    unsigned long long acc[8][2];
#pragma unroll
    for (int m = 0; m < 8; m++) { acc[m][0] = 0ull; acc[m][1] = 0ull; }

    for (int c = 0; c < 2; c++) {
        int gi0 = c * SK;
        if (myrow < NN) {
            const float4* s4 = reinterpret_cast<const float4*>(h + (size_t)myrow * 64 + gi0);
#pragma unroll
            for (int q = 0; q < SK / 4; q++) {
                float4 v = s4[q];
                hst[q * 4 + 0][tid] = v.x;
                hst[q * 4 + 1][tid] = v.y;
                hst[q * 4 + 2][tid] = v.z;
                hst[q * 4 + 3][tid] = v.w;
            }
        } else {
#pragma unroll
            for (int q = 0; q < SK; q++) hst[q][tid] = 0.f;
        }
        for (int idx = tid; idx < SK * 32; idx += BM) {
            int il = idx >> 5, cc = idx & 31;
            int k = cc >> 3, j = cc & 7;
            ws[il][cc] = Wl[k * 512 + (gi0 + il) * 8 + j];
        }
        __syncthreads();

#pragma unroll
        for (int i = 0; i < SK; i++) {
            float4 ha = *reinterpret_cast<const float4*>(&hst[i][trow * 8]);
            float4 hc = *reinterpret_cast<const float4*>(&hst[i][trow * 8 + 4]);
            unsigned long long hd[8];
            hd[0] = pk2(ha.x, ha.x); hd[1] = pk2(ha.y, ha.y);
            hd[2] = pk2(ha.z, ha.z); hd[3] = pk2(ha.w, ha.w);
            hd[4] = pk2(hc.x, hc.x); hd[5] = pk2(hc.y, hc.y);
            hd[6] = pk2(hc.z, hc.z); hd[7] = pk2(hc.w, hc.w);
            float4 w4 = *reinterpret_cast<const float4*>(&ws[i][tcol * 4]);
            unsigned long long wv0 = pk2(w4.x, w4.y);
            unsigned long long wv1 = pk2(w4.z, w4.w);
#pragma unroll
            for (int m = 0; m < 8; m++) {
                fma2(acc[m][0], hd[m], wv0);
                fma2(acc[m][1], hd[m], wv1);
            }
        }
        __syncthreads();
    }

#pragma unroll
    for (int m = 0; m < 8; m++) {
        int r = row0 + trow * 8 + m;
        if (r < NN) {
            float2 v0 = upk2(acc[m][0]);
            float2 v1 = upk2(acc[m][1]);
            float4 o = make_float4(v0.x, v0.y, v1.x, v1.y);
            *reinterpret_cast<float4*>(&Y[(size_t)r * 32 + tcol * 4]) = o;
        }
    }
}

// ---------------- launch ----------------
extern "C" void kernel_launch(void* const* d_in, const int* in_sizes, int n_in,
                              void* d_out, int out_size) {
    const float* x  = (const float*)d_in[0];
    const int*   ei = (const int*)d_in[1];     // int32! (JAX x64 disabled)
    const float* ea = (const float*)d_in[2];
    const float* W1 = (const float*)d_in[3];
    const float* b1 = (const float*)d_in[4];
    const float* W2 = (const float*)d_in[5];
    const float* b2 = (const float*)d_in[6];
    const float* Wf = (const float*)d_in[7];
    const float* bf = (const float*)d_in[8];
    const float* Wm = (const float*)d_in[9];
    const float* bm = (const float*)d_in[10];
    const float* Wl = (const float*)d_in[11];
    const float* bl = (const float*)d_in[12];
    float*       out = (float*)d_out;

    const int NB_N   = (NN + 255) / 256;
    const int NB_E   = (NE + 255) / 256;
    const int NB_P64 = (NN * 32 + 255) / 256;
    const int NB_P16 = (NN * 16 + 255) / 256;
    const int NB_P8  = (NN * 8 + 255) / 256;
    const int NB_G   = (NN + 127) / 128;

    // preprocessing: edge weights, gcn norm (dinv in scan1), CSR build
    k_zero<<<NB_N, 256>>>();
    k_edge<<<NB_E, 256>>>(ea, ei, W1, b1, W2, b2);
    k_scan1<<<SCAN_NBLK, SCAN_B>>>();
    k_scan2<<<1, 128>>>();
    k_scan3<<<SCAN_NBLK, SCAN_B>>>();
    k_fill<<<NB_E, 256>>>(ei);

    // layer 0: FIN=16 -> 64, relu; GEMM also emits fp16 seed into g_nh[0]
    k_prop16<<<NB_P16, 256>>>(x, -1, 0);
    k_prop16<<<NB_P16, 256>>>(nullptr, 0, 1);
    k_prop16<<<NB_P16, 256>>>(nullptr, 1, 2);
    k_gemm<16, 64, 16, true, true><<<NB_G, 128>>>(x, -1, Wf, bf, nullptr, 3, 0);

    // mid layer 0: fp16 hop chain nh0 -> nh1 -> nh0; fp32 hop results in bufs 0,1,2
    k_prop64h<<<NB_P64, 256>>>(0, 1, 0);
    k_prop64h<<<NB_P64, 256>>>(1, 0, 1);
    k_prop64h<<<NB_P64, 256>>>(0, -1, 2);
    k_gemm<64, 64, 32, true, true><<<NB_G, 128>>>(nullptr, 3, Wm, bm, nullptr, 4, 0);

    // mid layer 1
    k_prop64h<<<NB_P64, 256>>>(0, 1, 0);
    k_prop64h<<<NB_P64, 256>>>(1, 0, 1);
    k_prop64h<<<NB_P64, 256>>>(0, -1, 2);
    k_gemm<64, 64, 32, true, false><<<NB_G, 128>>>(nullptr, 4, Wm + 4 * 64 * 64, bm + 64, nullptr, 3, 0);

    // last layer via Horner: Y = h @ [W0|W1|W2|W3]  (N x 32), then 3 hops at F=8 (fp32)
    k_gemmY<<<NB_G, 128>>>(3, 4, Wl);
    // T1 = A*Y3 + Y2   (buf0)
    k_prop8<<<NB_P8, 256>>>(4, 24, 32, 4, 16, 32, nullptr, nullptr, 0);
    // T2 = A*T1 + Y1   (buf1)
    k_prop8<<<NB_P8, 256>>>(0, 0, 8, 4, 8, 32, nullptr, nullptr, 1);
    // out = A*T2 + Y0 + b
    k_prop8<<<NB_P8, 256>>>(1, 0, 8, 4, 0, 32, bl, out, -1);
}

// round 8
// speedup vs baseline: 1.5252x; 1.0699x over previous
#include <cuda_runtime.h>
#include <cuda_fp16.h>

#define NN 50000
#define NE 800000
#define SCAN_B 512
#define SCAN_NBLK ((NN + SCAN_B - 1) / SCAN_B)   // 98

// ---------------- packed f32x2 helpers (FFMA2 — only reachable via PTX) ----------------
__device__ __forceinline__ unsigned long long pk2(float a, float b) {
    unsigned long long r;
    asm("mov.b64 %0, {%1, %2};" : "=l"(r) : "f"(a), "f"(b));
    return r;
}
__device__ __forceinline__ void fma2(unsigned long long& d, unsigned long long a, unsigned long long b) {
    asm("fma.rn.f32x2 %0, %1, %2, %0;" : "+l"(d) : "l"(a), "l"(b));
}
__device__ __forceinline__ float2 upk2(unsigned long long v) {
    float2 r;
    asm("mov.b64 {%0, %1}, %2;" : "=f"(r.x), "=f"(r.y) : "l"(v));
    return r;
}

// ---------------- scratch (static device globals; no allocs) ----------------
__device__ float g_ew[NE];
__device__ float g_deg[NN];
__device__ float g_dinv[NN];
__device__ int   g_cnt[NN];
__device__ int   g_rowptr[NN + 1];
__device__ int   g_cur[NN];
__device__ int   g_csr_src[NE];
__device__ float g_csr_w[NE];
__device__ int   g_psum[SCAN_NBLK];
__device__ int   g_poff[SCAN_NBLK];
// fp32 buffers [NN x 64]: 3,4 = layer ping-pong / Y; 0,1 = prop8 temps
struct alignas(16) NFBuf { float v[5][NN * 64]; };
__device__ NFBuf g_nf;
// fp16 F=64 chain: idx 0 = seed (gemm epilogue), 1..3 = hops (gemm operands)
struct alignas(16) NH64 { __half2 v[4][NN * 32]; };
__device__ NH64 g_nh64;
// fp16 F=16 chain (layer 0): idx 0 = x fp16, 1..3 = hops
struct alignas(16) NH16 { __half2 v[4][NN * 8]; };
__device__ NH16 g_nh16;

// ---------------- init ----------------
__global__ void k_zero() {
    int i = blockIdx.x * blockDim.x + threadIdx.x;
    if (i < NN) { g_deg[i] = 0.f; g_cnt[i] = 0; }
}

// ---------------- edge MLP -> ew, plus deg & count histograms ----------------
// NOTE: edge_index is int32 (JAX x64 disabled downcasts jnp.int64 -> int32).
__global__ void k_edge(const float* __restrict__ ea, const int* __restrict__ ei,
                       const float* __restrict__ W1, const float* __restrict__ b1,
                       const float* __restrict__ W2, const float* __restrict__ b2) {
    __shared__ float sW1[512];
    __shared__ float sb1[64];
    __shared__ float sW2[64];
    __shared__ float sb2;
    for (int i = threadIdx.x; i < 512; i += blockDim.x) sW1[i] = W1[i];
    if (threadIdx.x < 64) { sb1[threadIdx.x] = b1[threadIdx.x]; sW2[threadIdx.x] = W2[threadIdx.x]; }
    if (threadIdx.x == 0) sb2 = b2[0];
    __syncthreads();

    int e = blockIdx.x * blockDim.x + threadIdx.x;
    if (e >= NE) return;

    float4 v0 = reinterpret_cast<const float4*>(ea)[e * 2];
    float4 v1 = reinterpret_cast<const float4*>(ea)[e * 2 + 1];
    float a[8] = {v0.x, v0.y, v0.z, v0.w, v1.x, v1.y, v1.z, v1.w};
    unsigned long long ad[8];
#pragma unroll
    for (int i = 0; i < 8; i++) ad[i] = pk2(a[i], a[i]);

    float ew = sb2;
#pragma unroll 8
    for (int j = 0; j < 64; j += 2) {
        unsigned long long h2 = pk2(sb1[j], sb1[j + 1]);
#pragma unroll
        for (int i = 0; i < 8; i++) {
            unsigned long long w2 = *reinterpret_cast<const unsigned long long*>(&sW1[i * 64 + j]);
            fma2(h2, ad[i], w2);
        }
        float2 h = upk2(h2);
        ew = fmaf(fmaxf(h.x, 0.f), sW2[j],     ew);
        ew = fmaf(fmaxf(h.y, 0.f), sW2[j + 1], ew);
    }
    g_ew[e] = ew;
    int dst = ei[NE + e];
    atomicAdd(&g_deg[dst], ew);
    atomicAdd(&g_cnt[dst], 1);
}

// ---------------- scan pass 1: block count reduce + dinv + x->fp16 ----------------
__global__ void k_scan1(const float* __restrict__ x) {
    __shared__ int red[SCAN_B / 32];
    int b = blockIdx.x, t = threadIdx.x;
    int i = b * SCAN_B + t;
    int c = (i < NN) ? g_cnt[i] : 0;
    if (i < NN) {
        float d = g_deg[i];
        g_dinv[i] = (d > 0.f) ? rsqrtf(d) : 0.f;
        // convert x row -> fp16 seed for layer-0 hop chain
        const float4* xr = reinterpret_cast<const float4*>(x + (size_t)i * 16);
        __half2 hr[8];
#pragma unroll
        for (int q = 0; q < 4; q++) {
            float4 v = xr[q];
            hr[q * 2]     = __floats2half2_rn(v.x, v.y);
            hr[q * 2 + 1] = __floats2half2_rn(v.z, v.w);
        }
        *reinterpret_cast<int4*>(&g_nh16.v[0][(size_t)i * 8])     = *reinterpret_cast<int4*>(&hr[0]);
        *reinterpret_cast<int4*>(&g_nh16.v[0][(size_t)i * 8 + 4]) = *reinterpret_cast<int4*>(&hr[4]);
    }
    int v = c;
#pragma unroll
    for (int o = 16; o; o >>= 1) v += __shfl_down_sync(0xffffffffu, v, o);
    if ((t & 31) == 0) red[t >> 5] = v;
    __syncthreads();
    if (t == 0) {
        int s = 0;
#pragma unroll
        for (int w = 0; w < SCAN_B / 32; w++) s += red[w];
        g_psum[b] = s;
    }
}
__global__ void k_scan2() {
    __shared__ int sc[128];
    int t = threadIdx.x;
    int c = (t < SCAN_NBLK) ? g_psum[t] : 0;
    sc[t] = c;
    __syncthreads();
#pragma unroll
    for (int off = 1; off < 128; off <<= 1) {
        int v = (t >= off) ? sc[t - off] : 0;
        __syncthreads();
        sc[t] += v;
        __syncthreads();
    }
    if (t < SCAN_NBLK) g_poff[t] = sc[t] - c;
    if (t == 127) g_rowptr[NN] = sc[127];   // == NE
}
__global__ void k_scan3() {
    __shared__ int sc[SCAN_B];
    int b = blockIdx.x, t = threadIdx.x;
    int i = b * SCAN_B + t;
    int c = (i < NN) ? g_cnt[i] : 0;
    sc[t] = c;
    __syncthreads();
#pragma unroll
    for (int off = 1; off < SCAN_B; off <<= 1) {
        int v = (t >= off) ? sc[t - off] : 0;
        __syncthreads();
        sc[t] += v;
        __syncthreads();
    }
    if (i < NN) {
        int excl = sc[t] - c + g_poff[b];
        g_rowptr[i] = excl;
        g_cur[i]    = excl;
    }
}

// ---------------- fill CSR (by dst) with fused normalized weight ----------------
__global__ void k_fill(const int* __restrict__ ei) {
    int e = blockIdx.x * blockDim.x + threadIdx.x;
    if (e >= NE) return;
    int src = ei[e];
    int dst = ei[NE + e];
    float w = g_dinv[src] * g_ew[e] * g_dinv[dst];
    int pos = atomicAdd(&g_cur[dst], 1);
    g_csr_src[pos] = src;
    g_csr_w[pos]   = w;
}

// ---------------- F=64 fp16 hop: warp/node, fp32 accum, fp16 out ----------------
__global__ void k_prop64h(int iidx, int oidx) {
    int g    = blockIdx.x * blockDim.x + threadIdx.x;
    int node = g >> 5;
    int lane = g & 31;
    if (node >= NN) return;
    const __half2* __restrict__ hin = g_nh64.v[iidx];
    __half2* __restrict__ hout = g_nh64.v[oidx];
    int beg = g_rowptr[node], end = g_rowptr[node + 1];
    float accx = 0.f, accy = 0.f;
    int p = beg;
    for (; p + 1 < end; p += 2) {
        int   s0 = g_csr_src[p],  s1 = g_csr_src[p + 1];
        float w0 = g_csr_w[p],    w1 = g_csr_w[p + 1];
        float2 f0 = __half22float2(hin[(size_t)s0 * 32 + lane]);
        float2 f1 = __half22float2(hin[(size_t)s1 * 32 + lane]);
        accx = fmaf(w0, f0.x, accx); accy = fmaf(w0, f0.y, accy);
        accx = fmaf(w1, f1.x, accx); accy = fmaf(w1, f1.y, accy);
    }
    if (p < end) {
        float w = g_csr_w[p];
        float2 f = __half22float2(hin[(size_t)g_csr_src[p] * 32 + lane]);
        accx = fmaf(w, f.x, accx); accy = fmaf(w, f.y, accy);
    }
    hout[(size_t)node * 32 + lane] = __floats2half2_rn(accx, accy);
}

// ---------------- F=16 fp16 hop: 8 threads/node (half2 per thread) ----------------
__global__ void k_prop16h(int iidx, int oidx) {
    int g    = blockIdx.x * blockDim.x + threadIdx.x;
    int node = g >> 3;
    int f    = g & 7;
    if (node >= NN) return;
    const __half2* __restrict__ hin = g_nh16.v[iidx];
    __half2* __restrict__ hout = g_nh16.v[oidx];
    int beg = g_rowptr[node], end = g_rowptr[node + 1];
    float accx = 0.f, accy = 0.f;
    int p = beg;
    for (; p + 1 < end; p += 2) {
        int   s0 = g_csr_src[p],  s1 = g_csr_src[p + 1];
        float w0 = g_csr_w[p],    w1 = g_csr_w[p + 1];
        float2 f0 = __half22float2(hin[(size_t)s0 * 8 + f]);
        float2 f1 = __half22float2(hin[(size_t)s1 * 8 + f]);
        accx = fmaf(w0, f0.x, accx); accy = fmaf(w0, f0.y, accy);
        accx = fmaf(w1, f1.x, accx); accy = fmaf(w1, f1.y, accy);
    }
    if (p < end) {
        float w = g_csr_w[p];
        float2 fv = __half22float2(hin[(size_t)g_csr_src[p] * 8 + f]);
        accx = fmaf(w, fv.x, accx); accy = fmaf(w, fv.y, accy);
    }
    hout[(size_t)node * 8 + f] = __floats2half2_rn(accx, accy);
}

// F=8 Horner hop (fp32, last layer): out[n] = (A tin)[n] + yadd[n] (+ bias)
__global__ void k_prop8(int tin_sel, int tin_off, int tin_stride,
                        int y_sel, int y_off, int y_stride,
                        const float* __restrict__ bias,
                        float* __restrict__ ext_out, int out_sel) {
    int g    = blockIdx.x * blockDim.x + threadIdx.x;
    int node = g >> 3;
    int f    = g & 7;
    if (node >= NN) return;
    const float* __restrict__ tin = g_nf.v[tin_sel] + tin_off;
    const float* __restrict__ ya  = g_nf.v[y_sel]  + y_off;
    float* __restrict__ outp = ext_out ? ext_out : g_nf.v[out_sel];
    int beg = g_rowptr[node], end = g_rowptr[node + 1];
    float acc0 = 0.f, acc1 = 0.f;
    int p = beg;
    for (; p + 1 < end; p += 2) {
        int   s0 = g_csr_src[p],  s1 = g_csr_src[p + 1];
        float w0 = g_csr_w[p],    w1 = g_csr_w[p + 1];
        acc0 = fmaf(w0, __ldg(tin + (size_t)s0 * tin_stride + f), acc0);
        acc1 = fmaf(w1, __ldg(tin + (size_t)s1 * tin_stride + f), acc1);
    }
    if (p < end)
        acc0 = fmaf(g_csr_w[p], __ldg(tin + (size_t)g_csr_src[p] * tin_stride + f), acc0);
    float v = acc0 + acc1 + ya[(size_t)node * y_stride + f];
    if (bias) v += bias[f];
    outp[(size_t)node * 8 + f] = v;
}

// ---------------- fused TAGConv GEMM (f32x2): out = [h | Ah | A2h | A3h] @ W + b -----
// k-chunk 0 (identity term) reads fp32; chunks for hops 1..3 read fp16 buffers.
// Optionally emits fp16 copy of out into g_nh64.v[0] (next layer's hop seed).
template <int FIN, int FOUT, int SK, bool RELU, bool HC>
__global__ void k_gemm(const float* __restrict__ ext0, int i0sel,
                       const float* __restrict__ W, const float* __restrict__ bias,
                       float* __restrict__ ext_out, int osel) {
    constexpr int BM  = 128;
    constexpr int KD  = 4 * FIN;
    constexpr int NCH = KD / SK;
    constexpr int TN  = FOUT / 8;
    constexpr int TP  = TN / 2;

    __shared__ float hst[SK][BM];       // transposed h tile
    __shared__ float ws[SK][FOUT];

    const float* h0 = (i0sel < 0) ? ext0 : g_nf.v[i0sel];
    float* out = (osel < 0) ? ext_out : g_nf.v[osel];

    int row0 = blockIdx.x * BM;
    int tid  = threadIdx.x;
    int trow = tid >> 3;
    int tcol = tid & 7;
    int myrow = row0 + tid;

    unsigned long long acc[8][TP];
#pragma unroll
    for (int m = 0; m < 8; m++)
#pragma unroll
        for (int n = 0; n < TP; n++) acc[m][n] = 0ull;

    for (int c = 0; c < NCH; c++) {
        int gi0 = c * SK;
        int bufidx = gi0 / FIN;         // 0 = identity (fp32), 1..3 = fp16 hops
        int off = gi0 % FIN;
        if (myrow < NN) {
            if (bufidx == 0) {
                const float4* s4 = reinterpret_cast<const float4*>(h0 + (size_t)myrow * FIN + off);
#pragma unroll
                for (int q = 0; q < SK / 4; q++) {
                    float4 v = s4[q];
                    hst[q * 4 + 0][tid] = v.x;
                    hst[q * 4 + 1][tid] = v.y;
                    hst[q * 4 + 2][tid] = v.z;
                    hst[q * 4 + 3][tid] = v.w;
                }
            } else {
                const __half2* hp2 = (FIN == 64) ? g_nh64.v[bufidx] : g_nh16.v[bufidx];
                const int4* s4h = reinterpret_cast<const int4*>(hp2 + (size_t)myrow * (FIN / 2) + off / 2);
#pragma unroll
                for (int q = 0; q < SK / 8; q++) {     // one int4 = 4 half2 = 8 k-values
                    int4 v = s4h[q];
                    float2 p0 = __half22float2(*reinterpret_cast<__half2*>(&v.x));
                    float2 p1 = __half22float2(*reinterpret_cast<__half2*>(&v.y));
                    float2 p2 = __half22float2(*reinterpret_cast<__half2*>(&v.z));
                    float2 p3 = __half22float2(*reinterpret_cast<__half2*>(&v.w));
                    hst[q * 8 + 0][tid] = p0.x; hst[q * 8 + 1][tid] = p0.y;
                    hst[q * 8 + 2][tid] = p1.x; hst[q * 8 + 3][tid] = p1.y;
                    hst[q * 8 + 4][tid] = p2.x; hst[q * 8 + 5][tid] = p2.y;
                    hst[q * 8 + 6][tid] = p3.x; hst[q * 8 + 7][tid] = p3.y;
                }
            }
        } else {
#pragma unroll
            for (int q = 0; q < SK; q++) hst[q][tid] = 0.f;
        }
        for (int idx = tid; idx < SK * FOUT; idx += BM)
            ((float*)ws)[idx] = W[gi0 * FOUT + idx];
        __syncthreads();

#pragma unroll
        for (int i = 0; i < SK; i++) {
            float4 ha = *reinterpret_cast<const float4*>(&hst[i][trow * 8]);
            float4 hc = *reinterpret_cast<const float4*>(&hst[i][trow * 8 + 4]);
            unsigned long long hd[8];
            hd[0] = pk2(ha.x, ha.x); hd[1] = pk2(ha.y, ha.y);
            hd[2] = pk2(ha.z, ha.z); hd[3] = pk2(ha.w, ha.w);
            hd[4] = pk2(hc.x, hc.x); hd[5] = pk2(hc.y, hc.y);
            hd[6] = pk2(hc.z, hc.z); hd[7] = pk2(hc.w, hc.w);
            unsigned long long wv[TP];
#pragma unroll
            for (int q = 0; q < TP / 2; q++) {
                float4 w4 = *reinterpret_cast<const float4*>(&ws[i][tcol * TN + q * 4]);
                wv[q * 2]     = pk2(w4.x, w4.y);
                wv[q * 2 + 1] = pk2(w4.z, w4.w);
            }
            if (TP & 1) {
                float2 w2 = *reinterpret_cast<const float2*>(&ws[i][tcol * TN + (TP - 1) * 2]);
                wv[TP - 1] = pk2(w2.x, w2.y);
            }
#pragma unroll
            for (int m = 0; m < 8; m++)
#pragma unroll
                for (int n = 0; n < TP; n++)
                    fma2(acc[m][n], hd[m], wv[n]);
        }
        __syncthreads();
    }

#pragma unroll
    for (int m = 0; m < 8; m++) {
        int r = row0 + trow * 8 + m;
        if (r < NN) {
#pragma unroll
            for (int n = 0; n < TP; n++) {
                float2 v = upk2(acc[m][n]);
                int j = tcol * TN + n * 2;
                float o0 = v.x + bias[j];
                float o1 = v.y + bias[j + 1];
                if (RELU) { o0 = fmaxf(o0, 0.f); o1 = fmaxf(o1, 0.f); }
                out[(size_t)r * FOUT + j]     = o0;
                out[(size_t)r * FOUT + j + 1] = o1;
                if (HC) g_nh64.v[0][(size_t)r * 32 + (j >> 1)] = __floats2half2_rn(o0, o1);
            }
        }
    }
}

// ---------------- last-layer Y GEMM (f32x2): Y[n][k*8+j] = sum_i h[n][i]*Wl[k][i][j] --
__global__ void k_gemmY(int isel, int osel, const float* __restrict__ Wl) {
    constexpr int BM = 128;
    constexpr int SK = 32;
    __shared__ float hst[SK][BM];
    __shared__ float ws[SK][32];

    const float* __restrict__ h = g_nf.v[isel];
    float* __restrict__ Y = g_nf.v[osel];

    int row0 = blockIdx.x * BM;
    int tid  = threadIdx.x;
    int trow = tid >> 3;
    int tcol = tid & 7;
    int myrow = row0 + tid;

    unsigned long long acc[8][2];
#pragma unroll
    for (int m = 0; m < 8; m++) { acc[m][0] = 0ull; acc[m][1] = 0ull; }

    for (int c = 0; c < 2; c++) {
        int gi0 = c * SK;
        if (myrow < NN) {
            const float4* s4 = reinterpret_cast<const float4*>(h + (size_t)myrow * 64 + gi0);
#pragma unroll
            for (int q = 0; q < SK / 4; q++) {
                float4 v = s4[q];
                hst[q * 4 + 0][tid] = v.x;
                hst[q * 4 + 1][tid] = v.y;
                hst[q * 4 + 2][tid] = v.z;
                hst[q * 4 + 3][tid] = v.w;
            }
        } else {
#pragma unroll
            for (int q = 0; q < SK; q++) hst[q][tid] = 0.f;
        }
        for (int idx = tid; idx < SK * 32; idx += BM) {
            int il = idx >> 5, cc = idx & 31;
            int k = cc >> 3, j = cc & 7;
            ws[il][cc] = Wl[k * 512 + (gi0 + il) * 8 + j];
        }
        __syncthreads();

#pragma unroll
        for (int i = 0; i < SK; i++) {
            float4 ha = *reinterpret_cast<const float4*>(&hst[i][trow * 8]);
            float4 hc = *reinterpret_cast<const float4*>(&hst[i][trow * 8 + 4]);
            unsigned long long hd[8];
            hd[0] = pk2(ha.x, ha.x); hd[1] = pk2(ha.y, ha.y);
            hd[2] = pk2(ha.z, ha.z); hd[3] = pk2(ha.w, ha.w);
            hd[4] = pk2(hc.x, hc.x); hd[5] = pk2(hc.y, hc.y);
            hd[6] = pk2(hc.z, hc.z); hd[7] = pk2(hc.w, hc.w);
            float4 w4 = *reinterpret_cast<const float4*>(&ws[i][tcol * 4]);
            unsigned long long wv0 = pk2(w4.x, w4.y);
            unsigned long long wv1 = pk2(w4.z, w4.w);
#pragma unroll
            for (int m = 0; m < 8; m++) {
                fma2(acc[m][0], hd[m], wv0);
                fma2(acc[m][1], hd[m], wv1);
            }
        }
        __syncthreads();
    }

#pragma unroll
    for (int m = 0; m < 8; m++) {
        int r = row0 + trow * 8 + m;
        if (r < NN) {
            float2 v0 = upk2(acc[m][0]);
            float2 v1 = upk2(acc[m][1]);
            float4 o = make_float4(v0.x, v0.y, v1.x, v1.y);
            *reinterpret_cast<float4*>(&Y[(size_t)r * 32 + tcol * 4]) = o;
        }
    }
}

// ---------------- launch ----------------
extern "C" void kernel_launch(void* const* d_in, const int* in_sizes, int n_in,
                              void* d_out, int out_size) {
    const float* x  = (const float*)d_in[0];
    const int*   ei = (const int*)d_in[1];     // int32! (JAX x64 disabled)
    const float* ea = (const float*)d_in[2];
    const float* W1 = (const float*)d_in[3];
    const float* b1 = (const float*)d_in[4];
    const float* W2 = (const float*)d_in[5];
    const float* b2 = (const float*)d_in[6];
    const float* Wf = (const float*)d_in[7];
    const float* bf = (const float*)d_in[8];
    const float* Wm = (const float*)d_in[9];
    const float* bm = (const float*)d_in[10];
    const float* Wl = (const float*)d_in[11];
    const float* bl = (const float*)d_in[12];
    float*       out = (float*)d_out;

    const int NB_N    = (NN + 255) / 256;
    const int NB_E    = (NE + 255) / 256;
    const int NB_P64  = (NN * 32 + 255) / 256;
    const int NB_P16H = (NN * 8 + 255) / 256;
    const int NB_P8   = (NN * 8 + 255) / 256;
    const int NB_G    = (NN + 127) / 128;

    // preprocessing: edge weights, gcn norm + x->fp16 (scan1), CSR build
    k_zero<<<NB_N, 256>>>();
    k_edge<<<NB_E, 256>>>(ea, ei, W1, b1, W2, b2);
    k_scan1<<<SCAN_NBLK, SCAN_B>>>(x);
    k_scan2<<<1, 128>>>();
    k_scan3<<<SCAN_NBLK, SCAN_B>>>();
    k_fill<<<NB_E, 256>>>(ei);

    // layer 0: fp16 hop chain nh16: 0->1->2->3; GEMM reads x fp32 + fp16 hops,
    // emits fp32 buf3 + fp16 seed nh64[0]
    k_prop16h<<<NB_P16H, 256>>>(0, 1);
    k_prop16h<<<NB_P16H, 256>>>(1, 2);
    k_prop16h<<<NB_P16H, 256>>>(2, 3);
    k_gemm<16, 64, 16, true, true><<<NB_G, 128>>>(x, -1, Wf, bf, nullptr, 3);

    // mid layer 0: nh64 0->1->2->3; GEMM reads fp32 buf3 + fp16 hops -> buf4 + seed
    k_prop64h<<<NB_P64, 256>>>(0, 1);
    k_prop64h<<<NB_P64, 256>>>(1, 2);
    k_prop64h<<<NB_P64, 256>>>(2, 3);
    k_gemm<64, 64, 32, true, true><<<NB_G, 128>>>(nullptr, 3, Wm, bm, nullptr, 4);

    // mid layer 1: -> buf3 (no seed; last layer is fp32)
    k_prop64h<<<NB_P64, 256>>>(0, 1);
    k_prop64h<<<NB_P64, 256>>>(1, 2);
    k_prop64h<<<NB_P64, 256>>>(2, 3);
    k_gemm<64, 64, 32, true, false><<<NB_G, 128>>>(nullptr, 4, Wm + 4 * 64 * 64, bm + 64, nullptr, 3);

    // last layer via Horner (fp32): Y = h @ [W0|W1|W2|W3], then 3 hops at F=8
    k_gemmY<<<NB_G, 128>>>(3, 4, Wl);
    // T1 = A*Y3 + Y2   (buf0)
    k_prop8<<<NB_P8, 256>>>(4, 24, 32, 4, 16, 32, nullptr, nullptr, 0);
    // T2 = A*T1 + Y1   (buf1)
    k_prop8<<<NB_P8, 256>>>(0, 0, 8, 4, 8, 32, nullptr, nullptr, 1);
    // out = A*T2 + Y0 + b
    k_prop8<<<NB_P8, 256>>>(1, 0, 8, 4, 0, 32, bl, out, -1);
}